// round 13
// baseline (speedup 1.0000x reference)
#include <cuda_runtime.h>
#include <cuda_bf16.h>
#include <cuda_fp16.h>
#include <stdint.h>
#include <stddef.h>
#include <math.h>

#define TOKENS 2048
#define DM 768
#define DFF 3072
#define NEXP 8
#define SEQ 1024
#define NH 12
#define BH 24
#define HD 64
#define NSLOTS (2 * TOKENS)

// ---------------- scratch (static device globals; no allocations) ----------------
__device__ __align__(16) unsigned short g_xn1b[TOKENS * DM];
__device__ __align__(16) float          g_xn2[TOKENS * DM];
__device__ __align__(16) unsigned short g_xn2b[TOKENS * DM];
__device__ __align__(16) unsigned short g_qb[TOKENS * DM];
__device__ __align__(16) unsigned short g_kb[TOKENS * DM];
__device__ __align__(16) unsigned short g_vb[TOKENS * DM];
__device__ __align__(16) unsigned short g_attnb[TOKENS * DM];
__device__ __align__(16) unsigned short g_hbuf[(size_t)NSLOTS * DFF];
// bf16 weights
__device__ __align__(16) unsigned short g_wqb[DM * DM];
__device__ __align__(16) unsigned short g_wkb[DM * DM];
__device__ __align__(16) unsigned short g_wvb[DM * DM];
__device__ __align__(16) unsigned short g_wob[DM * DM];
__device__ __align__(16) unsigned short g_w1b[(size_t)NEXP * DM * DFF];
__device__ __align__(16) unsigned short g_w2b[(size_t)NEXP * DFF * DM];
// routing
__device__ int   g_cnt[NEXP];
__device__ int   g_off[NEXP];
__device__ int   g_fill[NEXP];
__device__ int   g_top_e[NSLOTS];
__device__ float g_top_g[NSLOTS];
__device__ int   g_slot_tok[NSLOTS];
__device__ float g_slot_gate[NSLOTS];

// ---------------- helpers ----------------
__global__ void zero_cnt_kernel() {
    int t = threadIdx.x;
    if (t < NEXP) { g_cnt[t] = 0; g_fill[t] = 0; }
}

__device__ __forceinline__ uint32_t smem_u32(const void* p) {
    return (uint32_t)__cvta_generic_to_shared(p);
}
__device__ __forceinline__ uint32_t packbf(float x, float y) {
    __nv_bfloat162 h = __floats2bfloat162_rn(x, y);
    return *(uint32_t*)&h;
}
__device__ __forceinline__ void cp16(uint32_t saddr, const void* g) {
    asm volatile("cp.async.cg.shared.global [%0], [%1], 16;" :: "r"(saddr), "l"(g));
}
__device__ __forceinline__ void cp16z(uint32_t saddr, const void* g, int sz) {
    asm volatile("cp.async.cg.shared.global [%0], [%1], 16, %2;" :: "r"(saddr), "l"(g), "r"(sz));
}
#define CP_COMMIT() asm volatile("cp.async.commit_group;")
#define CP_WAIT(N)  asm volatile("cp.async.wait_group %0;" :: "n"(N))

__device__ __forceinline__ void ldsm_x4(uint32_t& r0, uint32_t& r1, uint32_t& r2, uint32_t& r3, uint32_t addr) {
    asm volatile("ldmatrix.sync.aligned.m8n8.x4.shared.b16 {%0,%1,%2,%3}, [%4];"
                 : "=r"(r0), "=r"(r1), "=r"(r2), "=r"(r3) : "r"(addr));
}
__device__ __forceinline__ void ldsm_x4_t(uint32_t& r0, uint32_t& r1, uint32_t& r2, uint32_t& r3, uint32_t addr) {
    asm volatile("ldmatrix.sync.aligned.m8n8.x4.trans.shared.b16 {%0,%1,%2,%3}, [%4];"
                 : "=r"(r0), "=r"(r1), "=r"(r2), "=r"(r3) : "r"(addr));
}
__device__ __forceinline__ void mma_bf16(float* c, uint32_t a0, uint32_t a1, uint32_t a2, uint32_t a3,
                                         uint32_t b0, uint32_t b1) {
    asm volatile("mma.sync.aligned.m16n8k16.row.col.f32.bf16.bf16.f32 "
                 "{%0,%1,%2,%3},{%4,%5,%6,%7},{%8,%9},{%0,%1,%2,%3};"
                 : "+f"(c[0]), "+f"(c[1]), "+f"(c[2]), "+f"(c[3])
                 : "r"(a0), "r"(a1), "r"(a2), "r"(a3), "r"(b0), "r"(b1));
}
__device__ __forceinline__ uint32_t ex2_f16x2(uint32_t a) {
    uint32_t r;
    asm volatile("ex2.approx.f16x2 %0, %1;" : "=r"(r) : "r"(a));
    return r;
}
__device__ __forceinline__ float gelu_exact(float x) {
    return 0.5f * x * (1.0f + erff(x * 0.70710678118654752f));
}

// ---------------- weight conversion (fp32 -> bf16) ----------------
__global__ void cvt_qkvo_kernel(const float* __restrict__ Wq, const float* __restrict__ Wk,
                                const float* __restrict__ Wv, const float* __restrict__ Wo) {
    int seg = blockIdx.y;
    const float* src = (seg == 0) ? Wq : (seg == 1) ? Wk : (seg == 2) ? Wv : Wo;
    unsigned short* dst = (seg == 0) ? g_wqb : (seg == 1) ? g_wkb : (seg == 2) ? g_wvb : g_wob;
    int i = (blockIdx.x * 256 + threadIdx.x) * 4;
    float4 v = *(const float4*)(src + i);
    *(uint2*)(dst + i) = make_uint2(packbf(v.x, v.y), packbf(v.z, v.w));
}
// merged W1+W2 conversion: GRID-STRIDE with small grid so it co-resides with
// the attention-phase kernels instead of monopolizing the SMs.
__global__ void cvt_moe_kernel(const float* __restrict__ W1, const float* __restrict__ W2,
                               unsigned short* __restrict__ d1, unsigned short* __restrict__ d2) {
    const size_t HALF = (size_t)NEXP * DM * DFF / 8;  // vec8 units per tensor
    const size_t TOT = 2 * HALF;
    for (size_t t = (size_t)blockIdx.x * 256 + threadIdx.x; t < TOT;
         t += (size_t)gridDim.x * 256) {
        const float* src;
        unsigned short* dst;
        size_t u = t;
        if (u < HALF) { src = W1; dst = d1; }
        else          { src = W2; dst = d2; u -= HALF; }
        size_t i = u * 8;
        float4 a = *(const float4*)(src + i);
        float4 b = *(const float4*)(src + i + 4);
        *(uint4*)(dst + i) = make_uint4(packbf(a.x, a.y), packbf(a.z, a.w),
                                        packbf(b.x, b.y), packbf(b.z, b.w));
    }
}

// ---------------- bf16 GEMM, cp.async 4-stage pipeline ----------------
// MODE 1: out = attnb @ Wo + bo + x          (fp32 out)
// MODE 2: hbuf = gelu(gather(xn2b) @ W1[e] + b1[e])
// MODE 3: out[tok] += gate * (hbuf @ W2[e] + b2[e])   (atomic)
// MODE 4: {qb,kb,vb} = xn1b @ {Wq,Wk,Wv}     (bf16 out, seg by blockIdx.x/6)
#define AS_EL(S, R, Cc) sm[(S) * 5120 + (R) * 40 + (Cc)]
#define BS_EL(S, R, Cc) sm[20480 + (S) * 4352 + (R) * 136 + (Cc)]

template<int MODE>
__global__ __launch_bounds__(256)
void bgemm(const float* __restrict__ bias, const float* __restrict__ res,
           float* __restrict__ C, int N, int Kdim) {
    extern __shared__ unsigned short sm[];
    int e = (MODE == 2 || MODE == 3) ? blockIdx.z : 0;
    int cnt = 0, off = 0;
    if (MODE == 2 || MODE == 3) {
        cnt = g_cnt[e];
        off = g_off[e];
        if ((int)blockIdx.y * 128 >= cnt) return;
    }
    const unsigned short* Bp;
    unsigned short* outp16 = nullptr;
    int m00 = blockIdx.y * 128;
    int col0 = blockIdx.x * 128;
    if (MODE == 1)      Bp = g_wob;
    else if (MODE == 2) Bp = g_w1b + (size_t)e * DM * DFF;
    else if (MODE == 3) Bp = g_w2b + (size_t)e * DFF * DM;
    else {  // MODE 4
        int seg = blockIdx.x / 6;
        Bp = (seg == 0) ? g_wqb : (seg == 1) ? g_wkb : g_wvb;
        outp16 = (seg == 0) ? g_qb : (seg == 1) ? g_kb : g_vb;
        col0 = (blockIdx.x % 6) * 128;
    }

    int tid = threadIdx.x, lane = tid & 31, warp = tid >> 5;
    int wm = (warp & 1) * 64, wn = (warp >> 1) * 32;
    int ar = tid >> 1, akc = (tid & 1) * 16;
    int bkr = tid >> 3, bc = (tid & 7) * 16;

    const unsigned short* abase;
    int azf = 16;
    if (MODE == 4)      abase = g_xn1b + (size_t)(m00 + ar) * DM;
    else if (MODE == 1) abase = g_attnb + (size_t)(m00 + ar) * DM;
    else if (MODE == 2) {
        int rc = m00 + ar;
        if (rc < cnt) abase = g_xn2b + (size_t)g_slot_tok[off + rc] * DM;
        else { abase = g_xn2b; azf = 0; }
    } else {
        int rc = m00 + ar;
        if (rc < cnt) abase = g_hbuf + (size_t)(off + rc) * DFF;
        else { abase = g_hbuf; azf = 0; }
    }
    const unsigned short* bbase = Bp + (size_t)bkr * N + col0 + bc;

#define ISSUE_TILE(S, K0)                                                   \
    do {                                                                    \
        uint32_t da = smem_u32(&AS_EL(S, ar, akc));                         \
        cp16z(da, abase + (K0) + akc, azf);                                 \
        cp16z(da + 16, abase + (K0) + akc + 8, azf);                        \
        uint32_t db = smem_u32(&BS_EL(S, bkr, bc));                         \
        const unsigned short* bs_ = bbase + (size_t)(K0) * N;               \
        cp16(db, bs_);                                                      \
        cp16(db + 16, bs_ + 8);                                             \
    } while (0)

    int nIter = Kdim >> 5;
    ISSUE_TILE(0, 0);  CP_COMMIT();
    ISSUE_TILE(1, 32); CP_COMMIT();
    ISSUE_TILE(2, 64); CP_COMMIT();

    float acc[4][4][4] = {};

    for (int it = 0; it < nIter; it++) {
        int stage = it & 3;
        CP_WAIT(2);
        __syncthreads();
        {
            int nt = it + 3;
            if (nt < nIter) ISSUE_TILE(nt & 3, nt << 5);
            CP_COMMIT();
        }
#pragma unroll
        for (int ks = 0; ks < 2; ks++) {
            int kk = ks * 16;
            uint32_t a[4][4];
#pragma unroll
            for (int mi = 0; mi < 4; mi++) {
                uint32_t addr = smem_u32(&AS_EL(stage, wm + mi * 16 + (lane & 15), kk + (lane >> 4) * 8));
                ldsm_x4(a[mi][0], a[mi][1], a[mi][2], a[mi][3], addr);
            }
            uint32_t b[4][2];
#pragma unroll
            for (int nb = 0; nb < 2; nb++) {
                uint32_t addr = smem_u32(&BS_EL(stage, kk + (lane & 15), wn + nb * 16 + (lane >> 4) * 8));
                ldsm_x4_t(b[nb * 2][0], b[nb * 2][1], b[nb * 2 + 1][0], b[nb * 2 + 1][1], addr);
            }
#pragma unroll
            for (int mi = 0; mi < 4; mi++)
#pragma unroll
                for (int nj = 0; nj < 4; nj++)
                    mma_bf16(acc[mi][nj], a[mi][0], a[mi][1], a[mi][2], a[mi][3],
                             b[nj][0], b[nj][1]);
        }
        __syncthreads();
    }
#undef ISSUE_TILE

    int g = lane >> 2, t4 = lane & 3;
#pragma unroll
    for (int mi = 0; mi < 4; mi++) {
#pragma unroll
        for (int h2 = 0; h2 < 2; h2++) {
            int rloc = wm + mi * 16 + g + h2 * 8;
            if (MODE == 2 || MODE == 3) {
                int rc = m00 + rloc;
                if (rc >= cnt) continue;
                int slot = off + rc;
                if (MODE == 2) {
                    size_t base = (size_t)slot * DFF;
#pragma unroll
                    for (int nj = 0; nj < 4; nj++) {
                        int col = col0 + wn + nj * 8 + 2 * t4;
                        float v0 = gelu_exact(acc[mi][nj][h2 * 2 + 0] + bias[(size_t)e * DFF + col]);
                        float v1 = gelu_exact(acc[mi][nj][h2 * 2 + 1] + bias[(size_t)e * DFF + col + 1]);
                        *(uint32_t*)&g_hbuf[base + col] = packbf(v0, v1);
                    }
                } else {
                    int tok = g_slot_tok[slot];
                    float gt = g_slot_gate[slot];
#pragma unroll
                    for (int nj = 0; nj < 4; nj++) {
                        int col = col0 + wn + nj * 8 + 2 * t4;
                        float v0 = (acc[mi][nj][h2 * 2 + 0] + bias[(size_t)e * DM + col]) * gt;
                        float v1 = (acc[mi][nj][h2 * 2 + 1] + bias[(size_t)e * DM + col + 1]) * gt;
                        atomicAdd(&C[(size_t)tok * DM + col], v0);
                        atomicAdd(&C[(size_t)tok * DM + col + 1], v1);
                    }
                }
            } else if (MODE == 1) {
                int row = m00 + rloc;
#pragma unroll
                for (int nj = 0; nj < 4; nj++) {
                    int col = col0 + wn + nj * 8 + 2 * t4;
                    float v0 = acc[mi][nj][h2 * 2 + 0] + bias[col] + res[(size_t)row * N + col];
                    float v1 = acc[mi][nj][h2 * 2 + 1] + bias[col + 1] + res[(size_t)row * N + col + 1];
                    *(float2*)&C[(size_t)row * N + col] = make_float2(v0, v1);
                }
            } else {  // MODE 4: bf16 out
                int row = m00 + rloc;
#pragma unroll
                for (int nj = 0; nj < 4; nj++) {
                    int col = col0 + wn + nj * 8 + 2 * t4;
                    *(uint32_t*)&outp16[(size_t)row * DM + col] =
                        packbf(acc[mi][nj][h2 * 2 + 0], acc[mi][nj][h2 * 2 + 1]);
                }
            }
        }
    }
}

// ---------------- fused flash attention: split-q, 32-row q-tiles, 64 threads ----
// grid (SEQ/32, BH). Per-warp math bitwise identical to the 64-row version.
__global__ __launch_bounds__(64)
void flash_attn_kernel() {
    int bh = blockIdx.y; int b = bh / NH, h = bh % NH;
    int qt = (int)(gridDim.x - 1) - (int)blockIdx.x;  // heavy tiles first
    int q0 = qt * 32;
    int nkv = (q0 + 95) >> 6;   // kv tiles of 64 covering keys <= q0+31
    int tid = threadIdx.x, lane = tid & 31, warp = tid >> 5;  // 2 warps
    int wq = warp * 16;

    __shared__ unsigned short Qs[32][72];
    __shared__ unsigned short Ks[2][64][72];
    __shared__ unsigned short Vs[2][64][72];

#define FA_ISSUE(BUF, K0)                                                          \
    do {                                                                           \
        const unsigned short* kp = g_kb + (size_t)(b * SEQ + (K0) + tid) * DM + h * HD; \
        const unsigned short* vp = g_vb + (size_t)(b * SEQ + (K0) + tid) * DM + h * HD; \
        uint32_t ka = smem_u32(&Ks[BUF][tid][0]);                                  \
        uint32_t va = smem_u32(&Vs[BUF][tid][0]);                                  \
        _Pragma("unroll")                                                          \
        for (int i_ = 0; i_ < 8; i_++) cp16(ka + 16 * i_, kp + 8 * i_);            \
        _Pragma("unroll")                                                          \
        for (int i_ = 0; i_ < 8; i_++) cp16(va + 16 * i_, vp + 8 * i_);            \
    } while (0)

    FA_ISSUE(0, 0);
    CP_COMMIT();

    // load Q tile (32 rows x 64 cols bf16); thread: row=tid>>1, half=(tid&1)*32
    {
        int lr = tid >> 1, lc = (tid & 1) * 32;
        const unsigned short* qp = g_qb + (size_t)(b * SEQ + q0 + lr) * DM + h * HD + lc;
        *(uint4*)&Qs[lr][lc]      = *(const uint4*)(qp);
        *(uint4*)&Qs[lr][lc + 8]  = *(const uint4*)(qp + 8);
        *(uint4*)&Qs[lr][lc + 16] = *(const uint4*)(qp + 16);
        *(uint4*)&Qs[lr][lc + 24] = *(const uint4*)(qp + 24);
    }
    __syncthreads();

    uint32_t qa[4][4];
#pragma unroll
    for (int kc = 0; kc < 4; kc++) {
        uint32_t addr = smem_u32(&Qs[wq + (lane & 15)][kc * 16 + (lane >> 4) * 8]);
        ldsm_x4(qa[kc][0], qa[kc][1], qa[kc][2], qa[kc][3], addr);
    }

    float m_run[2] = {-1e30f, -1e30f};
    float l_run[2] = {0.f, 0.f};
    float oacc[8][4] = {};

    for (int kt = 0; kt < nkv; kt++) {
        int k0 = kt * 64;
        int buf = kt & 1;
        CP_WAIT(0);
        __syncthreads();
        if (kt + 1 < nkv) { FA_ISSUE(buf ^ 1, k0 + 64); CP_COMMIT(); }

        // S = Q K^T
        float sacc[8][4] = {};
#pragma unroll
        for (int kc = 0; kc < 4; kc++) {
#pragma unroll
            for (int nb = 0; nb < 4; nb++) {
                uint32_t r0, r1, r2, r3;
                uint32_t addr = smem_u32(&Ks[buf][nb * 16 + (lane & 7) + ((lane >> 3) & 1) * 8]
                                            [kc * 16 + (lane >> 4) * 8]);
                ldsm_x4(r0, r1, r2, r3, addr);
                mma_bf16(sacc[nb * 2],     qa[kc][0], qa[kc][1], qa[kc][2], qa[kc][3], r0, r2);
                mma_bf16(sacc[nb * 2 + 1], qa[kc][0], qa[kc][1], qa[kc][2], qa[kc][3], r1, r3);
            }
        }

        // online softmax: exp via ex2.approx.f16x2
        bool diag = (kt == nkv - 1);
#pragma unroll
        for (int half = 0; half < 2; half++) {
            int qrow = q0 + wq + (lane >> 2) + half * 8;
            float vals[16];
#pragma unroll
            for (int nj = 0; nj < 8; nj++) {
                int colg = k0 + nj * 8 + 2 * (lane & 3);
                float v0 = sacc[nj][half * 2 + 0] * 0.125f;
                float v1 = sacc[nj][half * 2 + 1] * 0.125f;
                if (diag) {
                    if (colg > qrow) v0 = -1e30f;
                    if (colg + 1 > qrow) v1 = -1e30f;
                }
                vals[nj * 2] = v0;
                vals[nj * 2 + 1] = v1;
            }
            float tmx = vals[0];
#pragma unroll
            for (int i = 1; i < 16; i++) tmx = fmaxf(tmx, vals[i]);
            tmx = fmaxf(tmx, __shfl_xor_sync(0xffffffffu, tmx, 1));
            tmx = fmaxf(tmx, __shfl_xor_sync(0xffffffffu, tmx, 2));
            float mnew = fmaxf(m_run[half], tmx);
            float corr = __expf(m_run[half] - mnew);
            float rsum = 0.f;
#pragma unroll
            for (int i = 0; i < 8; i++) {
                float t0 = (vals[2 * i + 0] - mnew) * 1.44269504f;
                float t1 = (vals[2 * i + 1] - mnew) * 1.44269504f;
                __half2 ht = __floats2half2_rn(t0, t1);
                uint32_t pb = ex2_f16x2(*(uint32_t*)&ht);
                float2 p = __half22float2(*(__half2*)&pb);
                vals[2 * i + 0] = p.x;
                vals[2 * i + 1] = p.y;
                rsum += p.x + p.y;
            }
            rsum += __shfl_xor_sync(0xffffffffu, rsum, 1);
            rsum += __shfl_xor_sync(0xffffffffu, rsum, 2);
            l_run[half] = l_run[half] * corr + rsum;
            m_run[half] = mnew;
#pragma unroll
            for (int nj = 0; nj < 8; nj++) {
                oacc[nj][half * 2 + 0] *= corr;
                oacc[nj][half * 2 + 1] *= corr;
                sacc[nj][half * 2 + 0] = vals[nj * 2];
                sacc[nj][half * 2 + 1] = vals[nj * 2 + 1];
            }
        }

        // O += P @ V
#pragma unroll
        for (int j = 0; j < 4; j++) {
            uint32_t pa0 = packbf(sacc[2 * j][0], sacc[2 * j][1]);
            uint32_t pa1 = packbf(sacc[2 * j][2], sacc[2 * j][3]);
            uint32_t pa2 = packbf(sacc[2 * j + 1][0], sacc[2 * j + 1][1]);
            uint32_t pa3 = packbf(sacc[2 * j + 1][2], sacc[2 * j + 1][3]);
#pragma unroll
            for (int nb = 0; nb < 2; nb++) {
                uint32_t b0, b1, b2, b3;
                uint32_t addr = smem_u32(&Vs[buf][j * 16 + (lane & 15)][nb * 32 + (lane >> 4) * 8]);
                ldsm_x4_t(b0, b1, b2, b3, addr);
                mma_bf16(oacc[nb * 4 + 0], pa0, pa1, pa2, pa3, b0, b1);
                mma_bf16(oacc[nb * 4 + 1], pa0, pa1, pa2, pa3, b2, b3);
                addr = smem_u32(&Vs[buf][j * 16 + (lane & 15)][nb * 32 + 16 + (lane >> 4) * 8]);
                ldsm_x4_t(b0, b1, b2, b3, addr);
                mma_bf16(oacc[nb * 4 + 2], pa0, pa1, pa2, pa3, b0, b1);
                mma_bf16(oacc[nb * 4 + 3], pa0, pa1, pa2, pa3, b2, b3);
            }
        }
    }
#undef FA_ISSUE

    // write O (bf16)
#pragma unroll
    for (int half = 0; half < 2; half++) {
        float inv = 1.0f / l_run[half];
        int row = q0 + wq + (lane >> 2) + half * 8;
        unsigned short* dst = g_attnb + (size_t)(b * SEQ + row) * DM + h * HD;
#pragma unroll
        for (int nj = 0; nj < 8; nj++) {
            int col = nj * 8 + 2 * (lane & 3);
            *(uint32_t*)&dst[col] = packbf(oacc[nj][half * 2 + 0] * inv,
                                           oacc[nj][half * 2 + 1] * inv);
        }
    }
}

// ---------------- layernorm: writes bf16 always, fp32 optionally ----------------
__global__ void ln_kernel(const float* __restrict__ x, const float* __restrict__ gam,
                          const float* __restrict__ bet, float* __restrict__ yf,
                          unsigned short* __restrict__ yb) {
    int row = blockIdx.x;
    int tid = threadIdx.x;  // 256
    __shared__ float sx[DM];
    __shared__ float red[256];
    const float* xr = x + (size_t)row * DM;
    float s = 0.f;
    for (int i = tid; i < DM; i += 256) { float v = xr[i]; sx[i] = v; s += v; }
    red[tid] = s; __syncthreads();
    for (int o = 128; o > 0; o >>= 1) { if (tid < o) red[tid] += red[tid + o]; __syncthreads(); }
    float m = red[0] * (1.0f / DM);
    __syncthreads();
    float s2 = 0.f;
    for (int i = tid; i < DM; i += 256) { float d = sx[i] - m; s2 += d * d; }
    red[tid] = s2; __syncthreads();
    for (int o = 128; o > 0; o >>= 1) { if (tid < o) red[tid] += red[tid + o]; __syncthreads(); }
    float var = red[0] * (1.0f / DM);
    float r = rsqrtf(var + 1e-5f);
    for (int i = tid; i < DM; i += 256) {
        float v = (sx[i] - m) * r * gam[i] + bet[i];
        if (yf) yf[(size_t)row * DM + i] = v;
        yb[(size_t)row * DM + i] = __bfloat16_as_ushort(__float2bfloat16(v));
    }
}

// ---------------- router ----------------
__global__ void router_kernel(const float* __restrict__ Wr, const float* __restrict__ br) {
    int t = blockIdx.x, tid = threadIdx.x;  // 64 threads
    float acc[NEXP] = {};
    const float* xr = g_xn2 + (size_t)t * DM;
    for (int d = tid; d < DM; d += 64) {
        float xv = xr[d];
        const float* w = Wr + (size_t)d * NEXP;
#pragma unroll
        for (int e = 0; e < NEXP; e++) acc[e] += xv * w[e];
    }
    __shared__ float sh[64][NEXP + 1];
#pragma unroll
    for (int e = 0; e < NEXP; e++) sh[tid][e] = acc[e];
    __syncthreads();
    if (tid < NEXP) {
        float s = br[tid];
        for (int i = 0; i < 64; i++) s += sh[i][tid];
        sh[0][tid] = s;
    }
    __syncthreads();
    if (tid == 0) {
        float l[NEXP];
#pragma unroll
        for (int e = 0; e < NEXP; e++) l[e] = sh[0][e];
        int i1 = 0;
        for (int e = 1; e < NEXP; e++) if (l[e] > l[i1]) i1 = e;
        int i2 = (i1 == 0) ? 1 : 0;
        for (int e = 0; e < NEXP; e++) if (e != i1 && l[e] > l[i2]) i2 = e;
        float g1 = 1.0f / (1.0f + expf(l[i2] - l[i1]));
        float g2 = 1.0f - g1;
        g_top_e[2 * t] = i1; g_top_g[2 * t] = g1;
        g_top_e[2 * t + 1] = i2; g_top_g[2 * t + 1] = g2;
        atomicAdd(&g_cnt[i1], 1);
        atomicAdd(&g_cnt[i2], 1);
    }
}

__global__ void offsets_kernel() {
    if (threadIdx.x == 0) {
        int acc = 0;
#pragma unroll
        for (int e = 0; e < NEXP; e++) { g_off[e] = acc; acc += g_cnt[e]; }
    }
}

__global__ void scatter_kernel() {
    int i = blockIdx.x * 256 + threadIdx.x;
    if (i >= NSLOTS) return;
    int e = g_top_e[i];
    int p = atomicAdd(&g_fill[e], 1);
    int slot = g_off[e] + p;
    g_slot_tok[slot] = i >> 1;
    g_slot_gate[slot] = g_top_g[i];
}

// ---------------- launch ----------------
extern "C" void kernel_launch(void* const* d_in, const int* in_sizes, int n_in,
                              void* d_out, int out_size) {
    const float* x     = (const float*)d_in[0];
    const float* ln1_g = (const float*)d_in[1];
    const float* ln1_b = (const float*)d_in[2];
    const float* Wq    = (const float*)d_in[3];
    const float* Wk    = (const float*)d_in[4];
    const float* Wv    = (const float*)d_in[5];
    const float* Wo    = (const float*)d_in[6];
    const float* bo    = (const float*)d_in[7];
    const float* ln2_g = (const float*)d_in[8];
    const float* ln2_b = (const float*)d_in[9];
    const float* Wr    = (const float*)d_in[10];
    const float* br    = (const float*)d_in[11];
    const float* W1    = (const float*)d_in[12];
    const float* b1    = (const float*)d_in[13];
    const float* W2    = (const float*)d_in[14];
    const float* b2    = (const float*)d_in[15];
    float* out = (float*)d_out;

    float* xn2_p;
    unsigned short *xn1b_p, *xn2b_p, *w1b_p, *w2b_p;
    cudaGetSymbolAddress((void**)&xn2_p, g_xn2);
    cudaGetSymbolAddress((void**)&xn1b_p, g_xn1b);
    cudaGetSymbolAddress((void**)&xn2b_p, g_xn2b);
    cudaGetSymbolAddress((void**)&w1b_p, g_w1b);
    cudaGetSymbolAddress((void**)&w2b_p, g_w2b);

    const int BG_SMEM = (4 * 5120 + 4 * 4352) * 2;  // 75776 B (4-stage)
    cudaFuncSetAttribute(bgemm<1>, cudaFuncAttributeMaxDynamicSharedMemorySize, BG_SMEM);
    cudaFuncSetAttribute(bgemm<2>, cudaFuncAttributeMaxDynamicSharedMemorySize, BG_SMEM);
    cudaFuncSetAttribute(bgemm<3>, cudaFuncAttributeMaxDynamicSharedMemorySize, BG_SMEM);
    cudaFuncSetAttribute(bgemm<4>, cudaFuncAttributeMaxDynamicSharedMemorySize, BG_SMEM);

    // lazy-created side stream + fork/join events
    static cudaStream_t s_side = nullptr;
    static cudaEvent_t s_fork = nullptr, s_join = nullptr;
    if (s_side == nullptr) {
        cudaStreamCreateWithFlags(&s_side, cudaStreamNonBlocking);
        cudaEventCreateWithFlags(&s_fork, cudaEventDisableTiming);
        cudaEventCreateWithFlags(&s_join, cudaEventDisableTiming);
    }

    // ---- fork: MoE weight conversion on a SMALL grid so it truly co-resides ----
    cudaEventRecord(s_fork, 0);
    cudaStreamWaitEvent(s_side, s_fork, 0);
    cvt_moe_kernel<<<240, 256, 0, s_side>>>(W1, W2, w1b_p, w2b_p);
    cudaEventRecord(s_join, s_side);

    // ---- main stream: attention phase ----
    zero_cnt_kernel<<<1, 32>>>();
    cvt_qkvo_kernel<<<dim3(576, 4), 256>>>(Wq, Wk, Wv, Wo);
    ln_kernel<<<TOKENS, 256>>>(x, ln1_g, ln1_b, nullptr, xn1b_p);

    // fused QKV (bf16 out)
    bgemm<4><<<dim3(18, TOKENS / 128), 256, BG_SMEM>>>(nullptr, nullptr, nullptr, DM, DM);

    // flash attention: split-q, 768 CTAs of 64 threads
    flash_attn_kernel<<<dim3(SEQ / 32, BH), 64>>>();

    // h = x + attn @ Wo + bo -> d_out (fp32)
    bgemm<1><<<dim3(DM / 128, TOKENS / 128), 256, BG_SMEM>>>(bo, x, out, DM, DM);

    ln_kernel<<<TOKENS, 256>>>(out, ln2_g, ln2_b, xn2_p, xn2b_p);

    router_kernel<<<TOKENS, 64>>>(Wr, br);
    offsets_kernel<<<1, 32>>>();
    scatter_kernel<<<(NSLOTS + 255) / 256, 256>>>();

    // ---- join: MoE GEMMs need converted W1/W2 ----
    cudaStreamWaitEvent(0, s_join, 0);

    bgemm<2><<<dim3(DFF / 128, TOKENS / 128, NEXP), 256, BG_SMEM>>>(b1, nullptr, nullptr, DFF, DM);
    bgemm<3><<<dim3(DM / 128, TOKENS / 128, NEXP), 256, BG_SMEM>>>(b2, nullptr, out, DM, DFF);
}

// round 14
// speedup vs baseline: 1.0986x; 1.0986x over previous
#include <cuda_runtime.h>
#include <cuda_bf16.h>
#include <cuda_fp16.h>
#include <stdint.h>
#include <stddef.h>
#include <math.h>

#define TOKENS 2048
#define DM 768
#define DFF 3072
#define NEXP 8
#define SEQ 1024
#define NH 12
#define BH 24
#define HD 64
#define NSLOTS (2 * TOKENS)

// ---------------- scratch (static device globals; no allocations) ----------------
__device__ __align__(16) unsigned short g_xn1b[TOKENS * DM];
__device__ __align__(16) float          g_xn2[TOKENS * DM];
__device__ __align__(16) unsigned short g_xn2b[TOKENS * DM];
__device__ __align__(16) unsigned short g_qb[TOKENS * DM];
__device__ __align__(16) unsigned short g_kb[TOKENS * DM];
__device__ __align__(16) unsigned short g_vb[TOKENS * DM];
__device__ __align__(16) unsigned short g_attnb[TOKENS * DM];
__device__ __align__(16) unsigned short g_hbuf[(size_t)NSLOTS * DFF];
// bf16 weights
__device__ __align__(16) unsigned short g_wqb[DM * DM];
__device__ __align__(16) unsigned short g_wkb[DM * DM];
__device__ __align__(16) unsigned short g_wvb[DM * DM];
__device__ __align__(16) unsigned short g_wob[DM * DM];
__device__ __align__(16) unsigned short g_w1b[(size_t)NEXP * DM * DFF];
__device__ __align__(16) unsigned short g_w2b[(size_t)NEXP * DFF * DM];
// routing
__device__ int   g_cnt[NEXP];
__device__ int   g_off[NEXP];
__device__ int   g_fill[NEXP];
__device__ int   g_top_e[NSLOTS];
__device__ float g_top_g[NSLOTS];
__device__ int   g_slot_tok[NSLOTS];
__device__ float g_slot_gate[NSLOTS];

// ---------------- helpers ----------------
__global__ void zero_cnt_kernel() {
    int t = threadIdx.x;
    if (t < NEXP) { g_cnt[t] = 0; g_fill[t] = 0; }
}

__device__ __forceinline__ uint32_t smem_u32(const void* p) {
    return (uint32_t)__cvta_generic_to_shared(p);
}
__device__ __forceinline__ uint32_t packbf(float x, float y) {
    __nv_bfloat162 h = __floats2bfloat162_rn(x, y);
    return *(uint32_t*)&h;
}
__device__ __forceinline__ void cp16(uint32_t saddr, const void* g) {
    asm volatile("cp.async.cg.shared.global [%0], [%1], 16;" :: "r"(saddr), "l"(g));
}
__device__ __forceinline__ void cp16z(uint32_t saddr, const void* g, int sz) {
    asm volatile("cp.async.cg.shared.global [%0], [%1], 16, %2;" :: "r"(saddr), "l"(g), "r"(sz));
}
#define CP_COMMIT() asm volatile("cp.async.commit_group;")
#define CP_WAIT(N)  asm volatile("cp.async.wait_group %0;" :: "n"(N))

__device__ __forceinline__ void ldsm_x4(uint32_t& r0, uint32_t& r1, uint32_t& r2, uint32_t& r3, uint32_t addr) {
    asm volatile("ldmatrix.sync.aligned.m8n8.x4.shared.b16 {%0,%1,%2,%3}, [%4];"
                 : "=r"(r0), "=r"(r1), "=r"(r2), "=r"(r3) : "r"(addr));
}
__device__ __forceinline__ void ldsm_x4_t(uint32_t& r0, uint32_t& r1, uint32_t& r2, uint32_t& r3, uint32_t addr) {
    asm volatile("ldmatrix.sync.aligned.m8n8.x4.trans.shared.b16 {%0,%1,%2,%3}, [%4];"
                 : "=r"(r0), "=r"(r1), "=r"(r2), "=r"(r3) : "r"(addr));
}
__device__ __forceinline__ void mma_bf16(float* c, uint32_t a0, uint32_t a1, uint32_t a2, uint32_t a3,
                                         uint32_t b0, uint32_t b1) {
    asm volatile("mma.sync.aligned.m16n8k16.row.col.f32.bf16.bf16.f32 "
                 "{%0,%1,%2,%3},{%4,%5,%6,%7},{%8,%9},{%0,%1,%2,%3};"
                 : "+f"(c[0]), "+f"(c[1]), "+f"(c[2]), "+f"(c[3])
                 : "r"(a0), "r"(a1), "r"(a2), "r"(a3), "r"(b0), "r"(b1));
}
__device__ __forceinline__ uint32_t ex2_f16x2(uint32_t a) {
    uint32_t r;
    asm volatile("ex2.approx.f16x2 %0, %1;" : "=r"(r) : "r"(a));
    return r;
}
__device__ __forceinline__ float gelu_exact(float x) {
    return 0.5f * x * (1.0f + erff(x * 0.70710678118654752f));
}

// ---------------- weight conversion (fp32 -> bf16) ----------------
__global__ void cvt_qkvo_kernel(const float* __restrict__ Wq, const float* __restrict__ Wk,
                                const float* __restrict__ Wv, const float* __restrict__ Wo) {
    int seg = blockIdx.y;
    const float* src = (seg == 0) ? Wq : (seg == 1) ? Wk : (seg == 2) ? Wv : Wo;
    unsigned short* dst = (seg == 0) ? g_wqb : (seg == 1) ? g_wkb : (seg == 2) ? g_wvb : g_wob;
    int i = (blockIdx.x * 256 + threadIdx.x) * 4;
    float4 v = *(const float4*)(src + i);
    *(uint2*)(dst + i) = make_uint2(packbf(v.x, v.y), packbf(v.z, v.w));
}
// merged W1+W2 conversion, full grid, one launch
__global__ void cvt_moe_kernel(const float* __restrict__ W1, const float* __restrict__ W2,
                               unsigned short* __restrict__ d1, unsigned short* __restrict__ d2) {
    const size_t HALF = (size_t)NEXP * DM * DFF / 8;  // vec8 units per tensor
    size_t t = (size_t)blockIdx.x * 256 + threadIdx.x;
    const float* src;
    unsigned short* dst;
    if (t < HALF) { src = W1; dst = d1; }
    else          { src = W2; dst = d2; t -= HALF; }
    size_t i = t * 8;
    float4 a = *(const float4*)(src + i);
    float4 b = *(const float4*)(src + i + 4);
    *(uint4*)(dst + i) = make_uint4(packbf(a.x, a.y), packbf(a.z, a.w),
                                    packbf(b.x, b.y), packbf(b.z, b.w));
}

// ---------------- bf16 GEMM, cp.async 4-stage pipeline ----------------
// MODE 1: out = attnb @ Wo + bo + x          (fp32 out)
// MODE 2: hbuf = gelu(gather(xn2b) @ W1[e] + b1[e])
// MODE 3: out[tok] += gate * (hbuf @ W2[e] + b2[e])   (atomic)
// MODE 4: {qb,kb,vb} = xn1b @ {Wq,Wk,Wv}     (bf16 out, seg by blockIdx.x/6)
#define AS_EL(S, R, Cc) sm[(S) * 5120 + (R) * 40 + (Cc)]
#define BS_EL(S, R, Cc) sm[20480 + (S) * 4352 + (R) * 136 + (Cc)]

template<int MODE>
__global__ __launch_bounds__(256)
void bgemm(const float* __restrict__ bias, const float* __restrict__ res,
           float* __restrict__ C, int N, int Kdim) {
    extern __shared__ unsigned short sm[];
    int e = (MODE == 2 || MODE == 3) ? blockIdx.z : 0;
    int cnt = 0, off = 0;
    if (MODE == 2 || MODE == 3) {
        cnt = g_cnt[e];
        off = g_off[e];
        if ((int)blockIdx.y * 128 >= cnt) return;
    }
    const unsigned short* Bp;
    unsigned short* outp16 = nullptr;
    int m00 = blockIdx.y * 128;
    int col0 = blockIdx.x * 128;
    if (MODE == 1)      Bp = g_wob;
    else if (MODE == 2) Bp = g_w1b + (size_t)e * DM * DFF;
    else if (MODE == 3) Bp = g_w2b + (size_t)e * DFF * DM;
    else {  // MODE 4
        int seg = blockIdx.x / 6;
        Bp = (seg == 0) ? g_wqb : (seg == 1) ? g_wkb : g_wvb;
        outp16 = (seg == 0) ? g_qb : (seg == 1) ? g_kb : g_vb;
        col0 = (blockIdx.x % 6) * 128;
    }

    int tid = threadIdx.x, lane = tid & 31, warp = tid >> 5;
    int wm = (warp & 1) * 64, wn = (warp >> 1) * 32;
    int ar = tid >> 1, akc = (tid & 1) * 16;
    int bkr = tid >> 3, bc = (tid & 7) * 16;

    const unsigned short* abase;
    int azf = 16;
    if (MODE == 4)      abase = g_xn1b + (size_t)(m00 + ar) * DM;
    else if (MODE == 1) abase = g_attnb + (size_t)(m00 + ar) * DM;
    else if (MODE == 2) {
        int rc = m00 + ar;
        if (rc < cnt) abase = g_xn2b + (size_t)g_slot_tok[off + rc] * DM;
        else { abase = g_xn2b; azf = 0; }
    } else {
        int rc = m00 + ar;
        if (rc < cnt) abase = g_hbuf + (size_t)(off + rc) * DFF;
        else { abase = g_hbuf; azf = 0; }
    }
    const unsigned short* bbase = Bp + (size_t)bkr * N + col0 + bc;

#define ISSUE_TILE(S, K0)                                                   \
    do {                                                                    \
        uint32_t da = smem_u32(&AS_EL(S, ar, akc));                         \
        cp16z(da, abase + (K0) + akc, azf);                                 \
        cp16z(da + 16, abase + (K0) + akc + 8, azf);                        \
        uint32_t db = smem_u32(&BS_EL(S, bkr, bc));                         \
        const unsigned short* bs_ = bbase + (size_t)(K0) * N;               \
        cp16(db, bs_);                                                      \
        cp16(db + 16, bs_ + 8);                                             \
    } while (0)

    int nIter = Kdim >> 5;
    ISSUE_TILE(0, 0);  CP_COMMIT();
    ISSUE_TILE(1, 32); CP_COMMIT();
    ISSUE_TILE(2, 64); CP_COMMIT();

    float acc[4][4][4] = {};

    for (int it = 0; it < nIter; it++) {
        int stage = it & 3;
        CP_WAIT(2);
        __syncthreads();
        {
            int nt = it + 3;
            if (nt < nIter) ISSUE_TILE(nt & 3, nt << 5);
            CP_COMMIT();
        }
#pragma unroll
        for (int ks = 0; ks < 2; ks++) {
            int kk = ks * 16;
            uint32_t a[4][4];
#pragma unroll
            for (int mi = 0; mi < 4; mi++) {
                uint32_t addr = smem_u32(&AS_EL(stage, wm + mi * 16 + (lane & 15), kk + (lane >> 4) * 8));
                ldsm_x4(a[mi][0], a[mi][1], a[mi][2], a[mi][3], addr);
            }
            uint32_t b[4][2];
#pragma unroll
            for (int nb = 0; nb < 2; nb++) {
                uint32_t addr = smem_u32(&BS_EL(stage, kk + (lane & 15), wn + nb * 16 + (lane >> 4) * 8));
                ldsm_x4_t(b[nb * 2][0], b[nb * 2][1], b[nb * 2 + 1][0], b[nb * 2 + 1][1], addr);
            }
#pragma unroll
            for (int mi = 0; mi < 4; mi++)
#pragma unroll
                for (int nj = 0; nj < 4; nj++)
                    mma_bf16(acc[mi][nj], a[mi][0], a[mi][1], a[mi][2], a[mi][3],
                             b[nj][0], b[nj][1]);
        }
        __syncthreads();
    }
#undef ISSUE_TILE

    int g = lane >> 2, t4 = lane & 3;
#pragma unroll
    for (int mi = 0; mi < 4; mi++) {
#pragma unroll
        for (int h2 = 0; h2 < 2; h2++) {
            int rloc = wm + mi * 16 + g + h2 * 8;
            if (MODE == 2 || MODE == 3) {
                int rc = m00 + rloc;
                if (rc >= cnt) continue;
                int slot = off + rc;
                if (MODE == 2) {
                    size_t base = (size_t)slot * DFF;
#pragma unroll
                    for (int nj = 0; nj < 4; nj++) {
                        int col = col0 + wn + nj * 8 + 2 * t4;
                        float v0 = gelu_exact(acc[mi][nj][h2 * 2 + 0] + bias[(size_t)e * DFF + col]);
                        float v1 = gelu_exact(acc[mi][nj][h2 * 2 + 1] + bias[(size_t)e * DFF + col + 1]);
                        *(uint32_t*)&g_hbuf[base + col] = packbf(v0, v1);
                    }
                } else {
                    int tok = g_slot_tok[slot];
                    float gt = g_slot_gate[slot];
#pragma unroll
                    for (int nj = 0; nj < 4; nj++) {
                        int col = col0 + wn + nj * 8 + 2 * t4;
                        float v0 = (acc[mi][nj][h2 * 2 + 0] + bias[(size_t)e * DM + col]) * gt;
                        float v1 = (acc[mi][nj][h2 * 2 + 1] + bias[(size_t)e * DM + col + 1]) * gt;
                        atomicAdd(&C[(size_t)tok * DM + col], v0);
                        atomicAdd(&C[(size_t)tok * DM + col + 1], v1);
                    }
                }
            } else if (MODE == 1) {
                int row = m00 + rloc;
#pragma unroll
                for (int nj = 0; nj < 4; nj++) {
                    int col = col0 + wn + nj * 8 + 2 * t4;
                    float v0 = acc[mi][nj][h2 * 2 + 0] + bias[col] + res[(size_t)row * N + col];
                    float v1 = acc[mi][nj][h2 * 2 + 1] + bias[col + 1] + res[(size_t)row * N + col + 1];
                    *(float2*)&C[(size_t)row * N + col] = make_float2(v0, v1);
                }
            } else {  // MODE 4: bf16 out
                int row = m00 + rloc;
#pragma unroll
                for (int nj = 0; nj < 4; nj++) {
                    int col = col0 + wn + nj * 8 + 2 * t4;
                    *(uint32_t*)&outp16[(size_t)row * DM + col] =
                        packbf(acc[mi][nj][h2 * 2 + 0], acc[mi][nj][h2 * 2 + 1]);
                }
            }
        }
    }
}

// ---------------- fused flash attention (R11 config: 64-row q-tiles, 128 thr) ----
__global__ __launch_bounds__(128)
void flash_attn_kernel() {
    int bh = blockIdx.y; int b = bh / NH, h = bh % NH;
    int qt = (int)(gridDim.x - 1) - (int)blockIdx.x;  // heavy tiles first
    int q0 = qt * 64;
    int tid = threadIdx.x, lane = tid & 31, warp = tid >> 5;
    int wq = warp * 16;

    __shared__ unsigned short Qs[64][72];
    __shared__ unsigned short Ks[2][64][72];
    __shared__ unsigned short Vs[2][64][72];

    int lr = tid >> 1, lc = (tid & 1) * 32;

#define FA_ISSUE(BUF, K0)                                                          \
    do {                                                                           \
        const unsigned short* kp = g_kb + (size_t)(b * SEQ + (K0) + lr) * DM + h * HD + lc; \
        const unsigned short* vp = g_vb + (size_t)(b * SEQ + (K0) + lr) * DM + h * HD + lc; \
        uint32_t ka = smem_u32(&Ks[BUF][lr][lc]);                                  \
        uint32_t va = smem_u32(&Vs[BUF][lr][lc]);                                  \
        cp16(ka, kp); cp16(ka + 16, kp + 8); cp16(ka + 32, kp + 16); cp16(ka + 48, kp + 24); \
        cp16(va, vp); cp16(va + 16, vp + 8); cp16(va + 32, vp + 16); cp16(va + 48, vp + 24); \
    } while (0)

    FA_ISSUE(0, 0);
    CP_COMMIT();

    {
        const unsigned short* qp = g_qb + (size_t)(b * SEQ + q0 + lr) * DM + h * HD + lc;
        *(uint4*)&Qs[lr][lc]      = *(const uint4*)(qp);
        *(uint4*)&Qs[lr][lc + 8]  = *(const uint4*)(qp + 8);
        *(uint4*)&Qs[lr][lc + 16] = *(const uint4*)(qp + 16);
        *(uint4*)&Qs[lr][lc + 24] = *(const uint4*)(qp + 24);
    }
    __syncthreads();

    uint32_t qa[4][4];
#pragma unroll
    for (int kc = 0; kc < 4; kc++) {
        uint32_t addr = smem_u32(&Qs[wq + (lane & 15)][kc * 16 + (lane >> 4) * 8]);
        ldsm_x4(qa[kc][0], qa[kc][1], qa[kc][2], qa[kc][3], addr);
    }

    float m_run[2] = {-1e30f, -1e30f};
    float l_run[2] = {0.f, 0.f};
    float oacc[8][4] = {};

    for (int kt = 0; kt <= qt; kt++) {
        int k0 = kt * 64;
        int buf = kt & 1;
        CP_WAIT(0);
        __syncthreads();
        if (kt < qt) { FA_ISSUE(buf ^ 1, k0 + 64); CP_COMMIT(); }

        // S = Q K^T
        float sacc[8][4] = {};
#pragma unroll
        for (int kc = 0; kc < 4; kc++) {
#pragma unroll
            for (int nb = 0; nb < 4; nb++) {
                uint32_t r0, r1, r2, r3;
                uint32_t addr = smem_u32(&Ks[buf][nb * 16 + (lane & 7) + ((lane >> 3) & 1) * 8]
                                            [kc * 16 + (lane >> 4) * 8]);
                ldsm_x4(r0, r1, r2, r3, addr);
                mma_bf16(sacc[nb * 2],     qa[kc][0], qa[kc][1], qa[kc][2], qa[kc][3], r0, r2);
                mma_bf16(sacc[nb * 2 + 1], qa[kc][0], qa[kc][1], qa[kc][2], qa[kc][3], r1, r3);
            }
        }

        // online softmax: exp via ex2.approx.f16x2
        bool diag = (kt == qt);
#pragma unroll
        for (int half = 0; half < 2; half++) {
            int qrow = q0 + wq + (lane >> 2) + half * 8;
            float vals[16];
#pragma unroll
            for (int nj = 0; nj < 8; nj++) {
                int colg = k0 + nj * 8 + 2 * (lane & 3);
                float v0 = sacc[nj][half * 2 + 0] * 0.125f;
                float v1 = sacc[nj][half * 2 + 1] * 0.125f;
                if (diag) {
                    if (colg > qrow) v0 = -1e30f;
                    if (colg + 1 > qrow) v1 = -1e30f;
                }
                vals[nj * 2] = v0;
                vals[nj * 2 + 1] = v1;
            }
            float tmx = vals[0];
#pragma unroll
            for (int i = 1; i < 16; i++) tmx = fmaxf(tmx, vals[i]);
            tmx = fmaxf(tmx, __shfl_xor_sync(0xffffffffu, tmx, 1));
            tmx = fmaxf(tmx, __shfl_xor_sync(0xffffffffu, tmx, 2));
            float mnew = fmaxf(m_run[half], tmx);
            float corr = __expf(m_run[half] - mnew);
            float rsum = 0.f;
#pragma unroll
            for (int i = 0; i < 8; i++) {
                float t0 = (vals[2 * i + 0] - mnew) * 1.44269504f;
                float t1 = (vals[2 * i + 1] - mnew) * 1.44269504f;
                __half2 ht = __floats2half2_rn(t0, t1);
                uint32_t pb = ex2_f16x2(*(uint32_t*)&ht);
                float2 p = __half22float2(*(__half2*)&pb);
                vals[2 * i + 0] = p.x;
                vals[2 * i + 1] = p.y;
                rsum += p.x + p.y;
            }
            rsum += __shfl_xor_sync(0xffffffffu, rsum, 1);
            rsum += __shfl_xor_sync(0xffffffffu, rsum, 2);
            l_run[half] = l_run[half] * corr + rsum;
            m_run[half] = mnew;
#pragma unroll
            for (int nj = 0; nj < 8; nj++) {
                oacc[nj][half * 2 + 0] *= corr;
                oacc[nj][half * 2 + 1] *= corr;
                sacc[nj][half * 2 + 0] = vals[nj * 2];
                sacc[nj][half * 2 + 1] = vals[nj * 2 + 1];
            }
        }

        // O += P @ V
#pragma unroll
        for (int j = 0; j < 4; j++) {
            uint32_t pa0 = packbf(sacc[2 * j][0], sacc[2 * j][1]);
            uint32_t pa1 = packbf(sacc[2 * j][2], sacc[2 * j][3]);
            uint32_t pa2 = packbf(sacc[2 * j + 1][0], sacc[2 * j + 1][1]);
            uint32_t pa3 = packbf(sacc[2 * j + 1][2], sacc[2 * j + 1][3]);
#pragma unroll
            for (int nb = 0; nb < 2; nb++) {
                uint32_t b0, b1, b2, b3;
                uint32_t addr = smem_u32(&Vs[buf][j * 16 + (lane & 15)][nb * 32 + (lane >> 4) * 8]);
                ldsm_x4_t(b0, b1, b2, b3, addr);
                mma_bf16(oacc[nb * 4 + 0], pa0, pa1, pa2, pa3, b0, b1);
                mma_bf16(oacc[nb * 4 + 1], pa0, pa1, pa2, pa3, b2, b3);
                addr = smem_u32(&Vs[buf][j * 16 + (lane & 15)][nb * 32 + 16 + (lane >> 4) * 8]);
                ldsm_x4_t(b0, b1, b2, b3, addr);
                mma_bf16(oacc[nb * 4 + 2], pa0, pa1, pa2, pa3, b0, b1);
                mma_bf16(oacc[nb * 4 + 3], pa0, pa1, pa2, pa3, b2, b3);
            }
        }
    }
#undef FA_ISSUE

    // write O (bf16)
#pragma unroll
    for (int half = 0; half < 2; half++) {
        float inv = 1.0f / l_run[half];
        int row = q0 + wq + (lane >> 2) + half * 8;
        unsigned short* dst = g_attnb + (size_t)(b * SEQ + row) * DM + h * HD;
#pragma unroll
        for (int nj = 0; nj < 8; nj++) {
            int col = nj * 8 + 2 * (lane & 3);
            *(uint32_t*)&dst[col] = packbf(oacc[nj][half * 2 + 0] * inv,
                                           oacc[nj][half * 2 + 1] * inv);
        }
    }
}

// ---------------- layernorm: 192 threads, float4, single-pass sum/sumsq ---------
__global__ __launch_bounds__(192)
void ln_kernel(const float* __restrict__ x, const float* __restrict__ gam,
               const float* __restrict__ bet, float* __restrict__ yf,
               unsigned short* __restrict__ yb) {
    int row = blockIdx.x;
    int tid = threadIdx.x;  // 192 = DM/4
    __shared__ float rs[6], rs2[6];
    float4 v = ((const float4*)(x + (size_t)row * DM))[tid];
    float s  = v.x + v.y + v.z + v.w;
    float s2 = v.x * v.x + v.y * v.y + v.z * v.z + v.w * v.w;
#pragma unroll
    for (int o = 16; o > 0; o >>= 1) {
        s  += __shfl_xor_sync(0xffffffffu, s,  o);
        s2 += __shfl_xor_sync(0xffffffffu, s2, o);
    }
    if ((tid & 31) == 0) { rs[tid >> 5] = s; rs2[tid >> 5] = s2; }
    __syncthreads();
    float ts = 0.f, ts2 = 0.f;
#pragma unroll
    for (int i = 0; i < 6; i++) { ts += rs[i]; ts2 += rs2[i]; }
    float m = ts * (1.0f / DM);
    float var = ts2 * (1.0f / DM) - m * m;
    float r = rsqrtf(var + 1e-5f);
    float4 g4 = ((const float4*)gam)[tid];
    float4 b4 = ((const float4*)bet)[tid];
    float4 o4;
    o4.x = (v.x - m) * r * g4.x + b4.x;
    o4.y = (v.y - m) * r * g4.y + b4.y;
    o4.z = (v.z - m) * r * g4.z + b4.z;
    o4.w = (v.w - m) * r * g4.w + b4.w;
    if (yf) ((float4*)(yf + (size_t)row * DM))[tid] = o4;
    *(uint2*)(yb + (size_t)row * DM + tid * 4) =
        make_uint2(packbf(o4.x, o4.y), packbf(o4.z, o4.w));
}

// ---------------- router ----------------
__global__ void router_kernel(const float* __restrict__ Wr, const float* __restrict__ br) {
    int t = blockIdx.x, tid = threadIdx.x;  // 64 threads
    float acc[NEXP] = {};
    const float* xr = g_xn2 + (size_t)t * DM;
    for (int d = tid; d < DM; d += 64) {
        float xv = xr[d];
        const float* w = Wr + (size_t)d * NEXP;
#pragma unroll
        for (int e = 0; e < NEXP; e++) acc[e] += xv * w[e];
    }
    __shared__ float sh[64][NEXP + 1];
#pragma unroll
    for (int e = 0; e < NEXP; e++) sh[tid][e] = acc[e];
    __syncthreads();
    if (tid < NEXP) {
        float s = br[tid];
        for (int i = 0; i < 64; i++) s += sh[i][tid];
        sh[0][tid] = s;
    }
    __syncthreads();
    if (tid == 0) {
        float l[NEXP];
#pragma unroll
        for (int e = 0; e < NEXP; e++) l[e] = sh[0][e];
        int i1 = 0;
        for (int e = 1; e < NEXP; e++) if (l[e] > l[i1]) i1 = e;
        int i2 = (i1 == 0) ? 1 : 0;
        for (int e = 0; e < NEXP; e++) if (e != i1 && l[e] > l[i2]) i2 = e;
        float g1 = 1.0f / (1.0f + expf(l[i2] - l[i1]));
        float g2 = 1.0f - g1;
        g_top_e[2 * t] = i1; g_top_g[2 * t] = g1;
        g_top_e[2 * t + 1] = i2; g_top_g[2 * t + 1] = g2;
        atomicAdd(&g_cnt[i1], 1);
        atomicAdd(&g_cnt[i2], 1);
    }
}

__global__ void offsets_kernel() {
    if (threadIdx.x == 0) {
        int acc = 0;
#pragma unroll
        for (int e = 0; e < NEXP; e++) { g_off[e] = acc; acc += g_cnt[e]; }
    }
}

__global__ void scatter_kernel() {
    int i = blockIdx.x * 256 + threadIdx.x;
    if (i >= NSLOTS) return;
    int e = g_top_e[i];
    int p = atomicAdd(&g_fill[e], 1);
    int slot = g_off[e] + p;
    g_slot_tok[slot] = i >> 1;
    g_slot_gate[slot] = g_top_g[i];
}

// ---------------- launch ----------------
extern "C" void kernel_launch(void* const* d_in, const int* in_sizes, int n_in,
                              void* d_out, int out_size) {
    const float* x     = (const float*)d_in[0];
    const float* ln1_g = (const float*)d_in[1];
    const float* ln1_b = (const float*)d_in[2];
    const float* Wq    = (const float*)d_in[3];
    const float* Wk    = (const float*)d_in[4];
    const float* Wv    = (const float*)d_in[5];
    const float* Wo    = (const float*)d_in[6];
    const float* bo    = (const float*)d_in[7];
    const float* ln2_g = (const float*)d_in[8];
    const float* ln2_b = (const float*)d_in[9];
    const float* Wr    = (const float*)d_in[10];
    const float* br    = (const float*)d_in[11];
    const float* W1    = (const float*)d_in[12];
    const float* b1    = (const float*)d_in[13];
    const float* W2    = (const float*)d_in[14];
    const float* b2    = (const float*)d_in[15];
    float* out = (float*)d_out;

    float* xn2_p;
    unsigned short *xn1b_p, *xn2b_p, *w1b_p, *w2b_p;
    cudaGetSymbolAddress((void**)&xn2_p, g_xn2);
    cudaGetSymbolAddress((void**)&xn1b_p, g_xn1b);
    cudaGetSymbolAddress((void**)&xn2b_p, g_xn2b);
    cudaGetSymbolAddress((void**)&w1b_p, g_w1b);
    cudaGetSymbolAddress((void**)&w2b_p, g_w2b);

    const int BG_SMEM = (4 * 5120 + 4 * 4352) * 2;  // 75776 B (4-stage)
    cudaFuncSetAttribute(bgemm<1>, cudaFuncAttributeMaxDynamicSharedMemorySize, BG_SMEM);
    cudaFuncSetAttribute(bgemm<2>, cudaFuncAttributeMaxDynamicSharedMemorySize, BG_SMEM);
    cudaFuncSetAttribute(bgemm<3>, cudaFuncAttributeMaxDynamicSharedMemorySize, BG_SMEM);
    cudaFuncSetAttribute(bgemm<4>, cudaFuncAttributeMaxDynamicSharedMemorySize, BG_SMEM);

    zero_cnt_kernel<<<1, 32>>>();
    // weight conversions (sequential, full grid — best-known config)
    cvt_qkvo_kernel<<<dim3(576, 4), 256>>>(Wq, Wk, Wv, Wo);
    cvt_moe_kernel<<<2 * 9216, 256>>>(W1, W2, w1b_p, w2b_p);

    ln_kernel<<<TOKENS, 192>>>(x, ln1_g, ln1_b, nullptr, xn1b_p);

    // fused QKV (bf16 out)
    bgemm<4><<<dim3(18, TOKENS / 128), 256, BG_SMEM>>>(nullptr, nullptr, nullptr, DM, DM);

    flash_attn_kernel<<<dim3(SEQ / 64, BH), 128>>>();

    // h = x + attn @ Wo + bo -> d_out (fp32)
    bgemm<1><<<dim3(DM / 128, TOKENS / 128), 256, BG_SMEM>>>(bo, x, out, DM, DM);

    ln_kernel<<<TOKENS, 192>>>(out, ln2_g, ln2_b, xn2_p, xn2b_p);

    router_kernel<<<TOKENS, 64>>>(Wr, br);
    offsets_kernel<<<1, 32>>>();
    scatter_kernel<<<(NSLOTS + 255) / 256, 256>>>();

    bgemm<2><<<dim3(DFF / 128, TOKENS / 128, NEXP), 256, BG_SMEM>>>(b1, nullptr, nullptr, DFF, DM);
    bgemm<3><<<dim3(DM / 128, TOKENS / 128, NEXP), 256, BG_SMEM>>>(b2, nullptr, out, DM, DFF);
}

// round 15
// speedup vs baseline: 1.0998x; 1.0011x over previous
#include <cuda_runtime.h>
#include <cuda_bf16.h>
#include <cuda_fp16.h>
#include <stdint.h>
#include <stddef.h>
#include <math.h>

#define TOKENS 2048
#define DM 768
#define DFF 3072
#define NEXP 8
#define SEQ 1024
#define NH 12
#define BH 24
#define HD 64
#define NSLOTS (2 * TOKENS)

// ---------------- scratch (static device globals; no allocations) ----------------
__device__ __align__(16) unsigned short g_xn1b[TOKENS * DM];
__device__ __align__(16) float          g_xn2[TOKENS * DM];
__device__ __align__(16) unsigned short g_xn2b[TOKENS * DM];
__device__ __align__(16) unsigned short g_qb[TOKENS * DM];
__device__ __align__(16) unsigned short g_kb[TOKENS * DM];
__device__ __align__(16) unsigned short g_vb[TOKENS * DM];
__device__ __align__(16) unsigned short g_attnb[TOKENS * DM];
__device__ __align__(16) unsigned short g_hbuf[(size_t)NSLOTS * DFF];
// split-KV flash partials
__device__ __align__(16) float  g_po[(size_t)2 * BH * 16 * 64 * 64];   // 12.6 MB
__device__ __align__(16) float2 g_pml[(size_t)2 * BH * SEQ];
// bf16 weights
__device__ __align__(16) unsigned short g_wqb[DM * DM];
__device__ __align__(16) unsigned short g_wkb[DM * DM];
__device__ __align__(16) unsigned short g_wvb[DM * DM];
__device__ __align__(16) unsigned short g_wob[DM * DM];
__device__ __align__(16) unsigned short g_w1b[(size_t)NEXP * DM * DFF];
__device__ __align__(16) unsigned short g_w2b[(size_t)NEXP * DFF * DM];
// routing
__device__ int   g_cnt[NEXP];
__device__ int   g_off[NEXP];
__device__ int   g_fill[NEXP];
__device__ int   g_top_e[NSLOTS];
__device__ float g_top_g[NSLOTS];
__device__ int   g_slot_tok[NSLOTS];
__device__ float g_slot_gate[NSLOTS];

// ---------------- helpers ----------------
__global__ void zero_cnt_kernel() {
    int t = threadIdx.x;
    if (t < NEXP) { g_cnt[t] = 0; g_fill[t] = 0; }
}

__device__ __forceinline__ uint32_t smem_u32(const void* p) {
    return (uint32_t)__cvta_generic_to_shared(p);
}
__device__ __forceinline__ uint32_t packbf(float x, float y) {
    __nv_bfloat162 h = __floats2bfloat162_rn(x, y);
    return *(uint32_t*)&h;
}
__device__ __forceinline__ void cp16(uint32_t saddr, const void* g) {
    asm volatile("cp.async.cg.shared.global [%0], [%1], 16;" :: "r"(saddr), "l"(g));
}
__device__ __forceinline__ void cp16z(uint32_t saddr, const void* g, int sz) {
    asm volatile("cp.async.cg.shared.global [%0], [%1], 16, %2;" :: "r"(saddr), "l"(g), "r"(sz));
}
#define CP_COMMIT() asm volatile("cp.async.commit_group;")
#define CP_WAIT(N)  asm volatile("cp.async.wait_group %0;" :: "n"(N))

__device__ __forceinline__ void ldsm_x4(uint32_t& r0, uint32_t& r1, uint32_t& r2, uint32_t& r3, uint32_t addr) {
    asm volatile("ldmatrix.sync.aligned.m8n8.x4.shared.b16 {%0,%1,%2,%3}, [%4];"
                 : "=r"(r0), "=r"(r1), "=r"(r2), "=r"(r3) : "r"(addr));
}
__device__ __forceinline__ void ldsm_x4_t(uint32_t& r0, uint32_t& r1, uint32_t& r2, uint32_t& r3, uint32_t addr) {
    asm volatile("ldmatrix.sync.aligned.m8n8.x4.trans.shared.b16 {%0,%1,%2,%3}, [%4];"
                 : "=r"(r0), "=r"(r1), "=r"(r2), "=r"(r3) : "r"(addr));
}
__device__ __forceinline__ void mma_bf16(float* c, uint32_t a0, uint32_t a1, uint32_t a2, uint32_t a3,
                                         uint32_t b0, uint32_t b1) {
    asm volatile("mma.sync.aligned.m16n8k16.row.col.f32.bf16.bf16.f32 "
                 "{%0,%1,%2,%3},{%4,%5,%6,%7},{%8,%9},{%0,%1,%2,%3};"
                 : "+f"(c[0]), "+f"(c[1]), "+f"(c[2]), "+f"(c[3])
                 : "r"(a0), "r"(a1), "r"(a2), "r"(a3), "r"(b0), "r"(b1));
}
__device__ __forceinline__ uint32_t ex2_f16x2(uint32_t a) {
    uint32_t r;
    asm volatile("ex2.approx.f16x2 %0, %1;" : "=r"(r) : "r"(a));
    return r;
}
__device__ __forceinline__ float gelu_exact(float x) {
    return 0.5f * x * (1.0f + erff(x * 0.70710678118654752f));
}

// ---------------- weight conversion (fp32 -> bf16) ----------------
__global__ void cvt_qkvo_kernel(const float* __restrict__ Wq, const float* __restrict__ Wk,
                                const float* __restrict__ Wv, const float* __restrict__ Wo) {
    int seg = blockIdx.y;
    const float* src = (seg == 0) ? Wq : (seg == 1) ? Wk : (seg == 2) ? Wv : Wo;
    unsigned short* dst = (seg == 0) ? g_wqb : (seg == 1) ? g_wkb : (seg == 2) ? g_wvb : g_wob;
    int i = (blockIdx.x * 256 + threadIdx.x) * 4;
    float4 v = *(const float4*)(src + i);
    *(uint2*)(dst + i) = make_uint2(packbf(v.x, v.y), packbf(v.z, v.w));
}
__global__ void cvt_moe_kernel(const float* __restrict__ W1, const float* __restrict__ W2,
                               unsigned short* __restrict__ d1, unsigned short* __restrict__ d2) {
    const size_t HALF = (size_t)NEXP * DM * DFF / 8;
    size_t t = (size_t)blockIdx.x * 256 + threadIdx.x;
    const float* src;
    unsigned short* dst;
    if (t < HALF) { src = W1; dst = d1; }
    else          { src = W2; dst = d2; t -= HALF; }
    size_t i = t * 8;
    float4 a = *(const float4*)(src + i);
    float4 b = *(const float4*)(src + i + 4);
    *(uint4*)(dst + i) = make_uint4(packbf(a.x, a.y), packbf(a.z, a.w),
                                    packbf(b.x, b.y), packbf(b.z, b.w));
}

// ---------------- bf16 GEMM, cp.async 4-stage pipeline ----------------
#define AS_EL(S, R, Cc) sm[(S) * 5120 + (R) * 40 + (Cc)]
#define BS_EL(S, R, Cc) sm[20480 + (S) * 4352 + (R) * 136 + (Cc)]

template<int MODE>
__global__ __launch_bounds__(256)
void bgemm(const float* __restrict__ bias, const float* __restrict__ res,
           float* __restrict__ C, int N, int Kdim) {
    extern __shared__ unsigned short sm[];
    int e = (MODE == 2 || MODE == 3) ? blockIdx.z : 0;
    int cnt = 0, off = 0;
    if (MODE == 2 || MODE == 3) {
        cnt = g_cnt[e];
        off = g_off[e];
        if ((int)blockIdx.y * 128 >= cnt) return;
    }
    const unsigned short* Bp;
    unsigned short* outp16 = nullptr;
    int m00 = blockIdx.y * 128;
    int col0 = blockIdx.x * 128;
    if (MODE == 1)      Bp = g_wob;
    else if (MODE == 2) Bp = g_w1b + (size_t)e * DM * DFF;
    else if (MODE == 3) Bp = g_w2b + (size_t)e * DFF * DM;
    else {
        int seg = blockIdx.x / 6;
        Bp = (seg == 0) ? g_wqb : (seg == 1) ? g_wkb : g_wvb;
        outp16 = (seg == 0) ? g_qb : (seg == 1) ? g_kb : g_vb;
        col0 = (blockIdx.x % 6) * 128;
    }

    int tid = threadIdx.x, lane = tid & 31, warp = tid >> 5;
    int wm = (warp & 1) * 64, wn = (warp >> 1) * 32;
    int ar = tid >> 1, akc = (tid & 1) * 16;
    int bkr = tid >> 3, bc = (tid & 7) * 16;

    const unsigned short* abase;
    int azf = 16;
    if (MODE == 4)      abase = g_xn1b + (size_t)(m00 + ar) * DM;
    else if (MODE == 1) abase = g_attnb + (size_t)(m00 + ar) * DM;
    else if (MODE == 2) {
        int rc = m00 + ar;
        if (rc < cnt) abase = g_xn2b + (size_t)g_slot_tok[off + rc] * DM;
        else { abase = g_xn2b; azf = 0; }
    } else {
        int rc = m00 + ar;
        if (rc < cnt) abase = g_hbuf + (size_t)(off + rc) * DFF;
        else { abase = g_hbuf; azf = 0; }
    }
    const unsigned short* bbase = Bp + (size_t)bkr * N + col0 + bc;

#define ISSUE_TILE(S, K0)                                                   \
    do {                                                                    \
        uint32_t da = smem_u32(&AS_EL(S, ar, akc));                         \
        cp16z(da, abase + (K0) + akc, azf);                                 \
        cp16z(da + 16, abase + (K0) + akc + 8, azf);                        \
        uint32_t db = smem_u32(&BS_EL(S, bkr, bc));                         \
        const unsigned short* bs_ = bbase + (size_t)(K0) * N;               \
        cp16(db, bs_);                                                      \
        cp16(db + 16, bs_ + 8);                                             \
    } while (0)

    int nIter = Kdim >> 5;
    ISSUE_TILE(0, 0);  CP_COMMIT();
    ISSUE_TILE(1, 32); CP_COMMIT();
    ISSUE_TILE(2, 64); CP_COMMIT();

    float acc[4][4][4] = {};

    for (int it = 0; it < nIter; it++) {
        int stage = it & 3;
        CP_WAIT(2);
        __syncthreads();
        {
            int nt = it + 3;
            if (nt < nIter) ISSUE_TILE(nt & 3, nt << 5);
            CP_COMMIT();
        }
#pragma unroll
        for (int ks = 0; ks < 2; ks++) {
            int kk = ks * 16;
            uint32_t a[4][4];
#pragma unroll
            for (int mi = 0; mi < 4; mi++) {
                uint32_t addr = smem_u32(&AS_EL(stage, wm + mi * 16 + (lane & 15), kk + (lane >> 4) * 8));
                ldsm_x4(a[mi][0], a[mi][1], a[mi][2], a[mi][3], addr);
            }
            uint32_t b[4][2];
#pragma unroll
            for (int nb = 0; nb < 2; nb++) {
                uint32_t addr = smem_u32(&BS_EL(stage, kk + (lane & 15), wn + nb * 16 + (lane >> 4) * 8));
                ldsm_x4_t(b[nb * 2][0], b[nb * 2][1], b[nb * 2 + 1][0], b[nb * 2 + 1][1], addr);
            }
#pragma unroll
            for (int mi = 0; mi < 4; mi++)
#pragma unroll
                for (int nj = 0; nj < 4; nj++)
                    mma_bf16(acc[mi][nj], a[mi][0], a[mi][1], a[mi][2], a[mi][3],
                             b[nj][0], b[nj][1]);
        }
        __syncthreads();
    }
#undef ISSUE_TILE

    int g = lane >> 2, t4 = lane & 3;
#pragma unroll
    for (int mi = 0; mi < 4; mi++) {
#pragma unroll
        for (int h2 = 0; h2 < 2; h2++) {
            int rloc = wm + mi * 16 + g + h2 * 8;
            if (MODE == 2 || MODE == 3) {
                int rc = m00 + rloc;
                if (rc >= cnt) continue;
                int slot = off + rc;
                if (MODE == 2) {
                    size_t base = (size_t)slot * DFF;
#pragma unroll
                    for (int nj = 0; nj < 4; nj++) {
                        int col = col0 + wn + nj * 8 + 2 * t4;
                        float v0 = gelu_exact(acc[mi][nj][h2 * 2 + 0] + bias[(size_t)e * DFF + col]);
                        float v1 = gelu_exact(acc[mi][nj][h2 * 2 + 1] + bias[(size_t)e * DFF + col + 1]);
                        *(uint32_t*)&g_hbuf[base + col] = packbf(v0, v1);
                    }
                } else {
                    int tok = g_slot_tok[slot];
                    float gt = g_slot_gate[slot];
#pragma unroll
                    for (int nj = 0; nj < 4; nj++) {
                        int col = col0 + wn + nj * 8 + 2 * t4;
                        float v0 = (acc[mi][nj][h2 * 2 + 0] + bias[(size_t)e * DM + col]) * gt;
                        float v1 = (acc[mi][nj][h2 * 2 + 1] + bias[(size_t)e * DM + col + 1]) * gt;
                        atomicAdd(&C[(size_t)tok * DM + col], v0);
                        atomicAdd(&C[(size_t)tok * DM + col + 1], v1);
                    }
                }
            } else if (MODE == 1) {
                int row = m00 + rloc;
#pragma unroll
                for (int nj = 0; nj < 4; nj++) {
                    int col = col0 + wn + nj * 8 + 2 * t4;
                    float v0 = acc[mi][nj][h2 * 2 + 0] + bias[col] + res[(size_t)row * N + col];
                    float v1 = acc[mi][nj][h2 * 2 + 1] + bias[col + 1] + res[(size_t)row * N + col + 1];
                    *(float2*)&C[(size_t)row * N + col] = make_float2(v0, v1);
                }
            } else {
                int row = m00 + rloc;
#pragma unroll
                for (int nj = 0; nj < 4; nj++) {
                    int col = col0 + wn + nj * 8 + 2 * t4;
                    *(uint32_t*)&outp16[(size_t)row * DM + col] =
                        packbf(acc[mi][nj][h2 * 2 + 0], acc[mi][nj][h2 * 2 + 1]);
                }
            }
        }
    }
}

// ---------------- split-KV flash attention: grid (16, BH, 2) --------------------
// chunk 0: kv tiles [0, mid), chunk 1: [mid, nkv) where nkv = qt+1, mid = (nkv+1)/2.
// Writes UNNORMALIZED partial O (fp32) + per-row (m, l) to g_po / g_pml.
__global__ __launch_bounds__(128)
void flash_attn_kernel() {
    int bh = blockIdx.y; int b = bh / NH, h = bh % NH;
    int qt = 15 - (int)blockIdx.x;  // heavy tiles first
    int q0 = qt * 64;
    int chunk = blockIdx.z;
    int nkv = qt + 1;
    int mid = (nkv + 1) >> 1;
    int kt0 = (chunk == 0) ? 0 : mid;
    int kt1 = (chunk == 0) ? mid : nkv;
    int tid = threadIdx.x, lane = tid & 31, warp = tid >> 5;
    int wq = warp * 16;

    float2* pml = g_pml + ((size_t)chunk * BH + bh) * SEQ + q0;
    if (kt0 >= kt1) {  // empty chunk: sentinel ml, no O written
        if (tid < 64) pml[tid] = make_float2(-1e30f, 0.f);
        return;
    }

    __shared__ unsigned short Qs[64][72];
    __shared__ unsigned short Ks[2][64][72];
    __shared__ unsigned short Vs[2][64][72];

    int lr = tid >> 1, lc = (tid & 1) * 32;

#define FA_ISSUE(BUF, K0)                                                          \
    do {                                                                           \
        const unsigned short* kp = g_kb + (size_t)(b * SEQ + (K0) + lr) * DM + h * HD + lc; \
        const unsigned short* vp = g_vb + (size_t)(b * SEQ + (K0) + lr) * DM + h * HD + lc; \
        uint32_t ka = smem_u32(&Ks[BUF][lr][lc]);                                  \
        uint32_t va = smem_u32(&Vs[BUF][lr][lc]);                                  \
        cp16(ka, kp); cp16(ka + 16, kp + 8); cp16(ka + 32, kp + 16); cp16(ka + 48, kp + 24); \
        cp16(va, vp); cp16(va + 16, vp + 8); cp16(va + 32, vp + 16); cp16(va + 48, vp + 24); \
    } while (0)

    FA_ISSUE(0, kt0 * 64);
    CP_COMMIT();

    {
        const unsigned short* qp = g_qb + (size_t)(b * SEQ + q0 + lr) * DM + h * HD + lc;
        *(uint4*)&Qs[lr][lc]      = *(const uint4*)(qp);
        *(uint4*)&Qs[lr][lc + 8]  = *(const uint4*)(qp + 8);
        *(uint4*)&Qs[lr][lc + 16] = *(const uint4*)(qp + 16);
        *(uint4*)&Qs[lr][lc + 24] = *(const uint4*)(qp + 24);
    }
    __syncthreads();

    uint32_t qa[4][4];
#pragma unroll
    for (int kc = 0; kc < 4; kc++) {
        uint32_t addr = smem_u32(&Qs[wq + (lane & 15)][kc * 16 + (lane >> 4) * 8]);
        ldsm_x4(qa[kc][0], qa[kc][1], qa[kc][2], qa[kc][3], addr);
    }

    float m_run[2] = {-1e30f, -1e30f};
    float l_run[2] = {0.f, 0.f};
    float oacc[8][4] = {};

    for (int kt = kt0; kt < kt1; kt++) {
        int k0 = kt * 64;
        int buf = (kt - kt0) & 1;
        CP_WAIT(0);
        __syncthreads();
        if (kt + 1 < kt1) { FA_ISSUE(buf ^ 1, k0 + 64); CP_COMMIT(); }

        float sacc[8][4] = {};
#pragma unroll
        for (int kc = 0; kc < 4; kc++) {
#pragma unroll
            for (int nb = 0; nb < 4; nb++) {
                uint32_t r0, r1, r2, r3;
                uint32_t addr = smem_u32(&Ks[buf][nb * 16 + (lane & 7) + ((lane >> 3) & 1) * 8]
                                            [kc * 16 + (lane >> 4) * 8]);
                ldsm_x4(r0, r1, r2, r3, addr);
                mma_bf16(sacc[nb * 2],     qa[kc][0], qa[kc][1], qa[kc][2], qa[kc][3], r0, r2);
                mma_bf16(sacc[nb * 2 + 1], qa[kc][0], qa[kc][1], qa[kc][2], qa[kc][3], r1, r3);
            }
        }

        bool diag = (kt == qt);  // global diagonal tile
#pragma unroll
        for (int half = 0; half < 2; half++) {
            int qrow = q0 + wq + (lane >> 2) + half * 8;
            float vals[16];
#pragma unroll
            for (int nj = 0; nj < 8; nj++) {
                int colg = k0 + nj * 8 + 2 * (lane & 3);
                float v0 = sacc[nj][half * 2 + 0] * 0.125f;
                float v1 = sacc[nj][half * 2 + 1] * 0.125f;
                if (diag) {
                    if (colg > qrow) v0 = -1e30f;
                    if (colg + 1 > qrow) v1 = -1e30f;
                }
                vals[nj * 2] = v0;
                vals[nj * 2 + 1] = v1;
            }
            float tmx = vals[0];
#pragma unroll
            for (int i = 1; i < 16; i++) tmx = fmaxf(tmx, vals[i]);
            tmx = fmaxf(tmx, __shfl_xor_sync(0xffffffffu, tmx, 1));
            tmx = fmaxf(tmx, __shfl_xor_sync(0xffffffffu, tmx, 2));
            float mnew = fmaxf(m_run[half], tmx);
            float corr = __expf(m_run[half] - mnew);
            float rsum = 0.f;
#pragma unroll
            for (int i = 0; i < 8; i++) {
                float t0 = (vals[2 * i + 0] - mnew) * 1.44269504f;
                float t1 = (vals[2 * i + 1] - mnew) * 1.44269504f;
                __half2 ht = __floats2half2_rn(t0, t1);
                uint32_t pb = ex2_f16x2(*(uint32_t*)&ht);
                float2 p = __half22float2(*(__half2*)&pb);
                vals[2 * i + 0] = p.x;
                vals[2 * i + 1] = p.y;
                rsum += p.x + p.y;
            }
            rsum += __shfl_xor_sync(0xffffffffu, rsum, 1);
            rsum += __shfl_xor_sync(0xffffffffu, rsum, 2);
            l_run[half] = l_run[half] * corr + rsum;
            m_run[half] = mnew;
#pragma unroll
            for (int nj = 0; nj < 8; nj++) {
                oacc[nj][half * 2 + 0] *= corr;
                oacc[nj][half * 2 + 1] *= corr;
                sacc[nj][half * 2 + 0] = vals[nj * 2];
                sacc[nj][half * 2 + 1] = vals[nj * 2 + 1];
            }
        }

#pragma unroll
        for (int j = 0; j < 4; j++) {
            uint32_t pa0 = packbf(sacc[2 * j][0], sacc[2 * j][1]);
            uint32_t pa1 = packbf(sacc[2 * j][2], sacc[2 * j][3]);
            uint32_t pa2 = packbf(sacc[2 * j + 1][0], sacc[2 * j + 1][1]);
            uint32_t pa3 = packbf(sacc[2 * j + 1][2], sacc[2 * j + 1][3]);
#pragma unroll
            for (int nb = 0; nb < 2; nb++) {
                uint32_t b0, b1, b2, b3;
                uint32_t addr = smem_u32(&Vs[buf][j * 16 + (lane & 15)][nb * 32 + (lane >> 4) * 8]);
                ldsm_x4_t(b0, b1, b2, b3, addr);
                mma_bf16(oacc[nb * 4 + 0], pa0, pa1, pa2, pa3, b0, b1);
                mma_bf16(oacc[nb * 4 + 1], pa0, pa1, pa2, pa3, b2, b3);
                addr = smem_u32(&Vs[buf][j * 16 + (lane & 15)][nb * 32 + 16 + (lane >> 4) * 8]);
                ldsm_x4_t(b0, b1, b2, b3, addr);
                mma_bf16(oacc[nb * 4 + 2], pa0, pa1, pa2, pa3, b0, b1);
                mma_bf16(oacc[nb * 4 + 3], pa0, pa1, pa2, pa3, b2, b3);
            }
        }
    }
#undef FA_ISSUE

    // write UNNORMALIZED partial O (fp32) + (m, l)
    float* po = g_po + (((size_t)chunk * BH + bh) * 16 + (size_t)qt) * 4096;
#pragma unroll
    for (int half = 0; half < 2; half++) {
        int rloc = wq + (lane >> 2) + half * 8;
        if ((lane & 3) == 0) pml[rloc] = make_float2(m_run[half], l_run[half]);
#pragma unroll
        for (int nj = 0; nj < 8; nj++) {
            int col = nj * 8 + 2 * (lane & 3);
            *(float2*)&po[rloc * 64 + col] =
                make_float2(oacc[nj][half * 2 + 0], oacc[nj][half * 2 + 1]);
        }
    }
}

// ---------------- flash combine: merge 2 partials -> bf16 attnb ------------------
__global__ __launch_bounds__(256)
void flash_combine_kernel() {
    int qt = blockIdx.x, bh = blockIdx.y;
    int b = bh / NH, h = bh % NH;
    int q0 = qt * 64;
    int tid = threadIdx.x;
    int r = tid >> 2, cseg = (tid & 3) * 16;

    float2 ml0 = g_pml[((size_t)0 * BH + bh) * SEQ + q0 + r];
    float2 ml1 = g_pml[((size_t)1 * BH + bh) * SEQ + q0 + r];
    bool v1 = ml1.y > 0.f;
    float mstar = fmaxf(ml0.x, v1 ? ml1.x : -1e30f);
    float e0 = __expf(ml0.x - mstar);
    float e1 = v1 ? __expf(ml1.x - mstar) : 0.f;
    float inv = 1.0f / (ml0.y * e0 + (v1 ? ml1.y * e1 : 0.f));

    const float* po0 = g_po + (((size_t)0 * BH + bh) * 16 + (size_t)qt) * 4096 + r * 64;
    const float* po1 = g_po + (((size_t)1 * BH + bh) * 16 + (size_t)qt) * 4096 + r * 64;
    unsigned short* dst = g_attnb + (size_t)(b * SEQ + q0 + r) * DM + h * HD;
#pragma unroll
    for (int i = 0; i < 4; i++) {
        int col = cseg + i * 4;
        float4 o0 = *(const float4*)(po0 + col);
        float4 o1 = v1 ? *(const float4*)(po1 + col) : make_float4(0.f, 0.f, 0.f, 0.f);
        float vx = (o0.x * e0 + o1.x * e1) * inv;
        float vy = (o0.y * e0 + o1.y * e1) * inv;
        float vz = (o0.z * e0 + o1.z * e1) * inv;
        float vw = (o0.w * e0 + o1.w * e1) * inv;
        *(uint2*)&dst[col] = make_uint2(packbf(vx, vy), packbf(vz, vw));
    }
}

// ---------------- layernorm: 192 threads, float4, single-pass sum/sumsq ---------
__global__ __launch_bounds__(192)
void ln_kernel(const float* __restrict__ x, const float* __restrict__ gam,
               const float* __restrict__ bet, float* __restrict__ yf,
               unsigned short* __restrict__ yb) {
    int row = blockIdx.x;
    int tid = threadIdx.x;  // 192 = DM/4
    __shared__ float rs[6], rs2[6];
    float4 v = ((const float4*)(x + (size_t)row * DM))[tid];
    float s  = v.x + v.y + v.z + v.w;
    float s2 = v.x * v.x + v.y * v.y + v.z * v.z + v.w * v.w;
#pragma unroll
    for (int o = 16; o > 0; o >>= 1) {
        s  += __shfl_xor_sync(0xffffffffu, s,  o);
        s2 += __shfl_xor_sync(0xffffffffu, s2, o);
    }
    if ((tid & 31) == 0) { rs[tid >> 5] = s; rs2[tid >> 5] = s2; }
    __syncthreads();
    float ts = 0.f, ts2 = 0.f;
#pragma unroll
    for (int i = 0; i < 6; i++) { ts += rs[i]; ts2 += rs2[i]; }
    float m = ts * (1.0f / DM);
    float var = ts2 * (1.0f / DM) - m * m;
    float r = rsqrtf(var + 1e-5f);
    float4 g4 = ((const float4*)gam)[tid];
    float4 b4 = ((const float4*)bet)[tid];
    float4 o4;
    o4.x = (v.x - m) * r * g4.x + b4.x;
    o4.y = (v.y - m) * r * g4.y + b4.y;
    o4.z = (v.z - m) * r * g4.z + b4.z;
    o4.w = (v.w - m) * r * g4.w + b4.w;
    if (yf) ((float4*)(yf + (size_t)row * DM))[tid] = o4;
    *(uint2*)(yb + (size_t)row * DM + tid * 4) =
        make_uint2(packbf(o4.x, o4.y), packbf(o4.z, o4.w));
}

// ---------------- router ----------------
__global__ void router_kernel(const float* __restrict__ Wr, const float* __restrict__ br) {
    int t = blockIdx.x, tid = threadIdx.x;  // 64 threads
    float acc[NEXP] = {};
    const float* xr = g_xn2 + (size_t)t * DM;
    for (int d = tid; d < DM; d += 64) {
        float xv = xr[d];
        const float* w = Wr + (size_t)d * NEXP;
#pragma unroll
        for (int e = 0; e < NEXP; e++) acc[e] += xv * w[e];
    }
    __shared__ float sh[64][NEXP + 1];
#pragma unroll
    for (int e = 0; e < NEXP; e++) sh[tid][e] = acc[e];
    __syncthreads();
    if (tid < NEXP) {
        float s = br[tid];
        for (int i = 0; i < 64; i++) s += sh[i][tid];
        sh[0][tid] = s;
    }
    __syncthreads();
    if (tid == 0) {
        float l[NEXP];
#pragma unroll
        for (int e = 0; e < NEXP; e++) l[e] = sh[0][e];
        int i1 = 0;
        for (int e = 1; e < NEXP; e++) if (l[e] > l[i1]) i1 = e;
        int i2 = (i1 == 0) ? 1 : 0;
        for (int e = 0; e < NEXP; e++) if (e != i1 && l[e] > l[i2]) i2 = e;
        float g1 = 1.0f / (1.0f + expf(l[i2] - l[i1]));
        float g2 = 1.0f - g1;
        g_top_e[2 * t] = i1; g_top_g[2 * t] = g1;
        g_top_e[2 * t + 1] = i2; g_top_g[2 * t + 1] = g2;
        atomicAdd(&g_cnt[i1], 1);
        atomicAdd(&g_cnt[i2], 1);
    }
}

__global__ void offsets_kernel() {
    if (threadIdx.x == 0) {
        int acc = 0;
#pragma unroll
        for (int e = 0; e < NEXP; e++) { g_off[e] = acc; acc += g_cnt[e]; }
    }
}

__global__ void scatter_kernel() {
    int i = blockIdx.x * 256 + threadIdx.x;
    if (i >= NSLOTS) return;
    int e = g_top_e[i];
    int p = atomicAdd(&g_fill[e], 1);
    int slot = g_off[e] + p;
    g_slot_tok[slot] = i >> 1;
    g_slot_gate[slot] = g_top_g[i];
}

// ---------------- launch ----------------
extern "C" void kernel_launch(void* const* d_in, const int* in_sizes, int n_in,
                              void* d_out, int out_size) {
    const float* x     = (const float*)d_in[0];
    const float* ln1_g = (const float*)d_in[1];
    const float* ln1_b = (const float*)d_in[2];
    const float* Wq    = (const float*)d_in[3];
    const float* Wk    = (const float*)d_in[4];
    const float* Wv    = (const float*)d_in[5];
    const float* Wo    = (const float*)d_in[6];
    const float* bo    = (const float*)d_in[7];
    const float* ln2_g = (const float*)d_in[8];
    const float* ln2_b = (const float*)d_in[9];
    const float* Wr    = (const float*)d_in[10];
    const float* br    = (const float*)d_in[11];
    const float* W1    = (const float*)d_in[12];
    const float* b1    = (const float*)d_in[13];
    const float* W2    = (const float*)d_in[14];
    const float* b2    = (const float*)d_in[15];
    float* out = (float*)d_out;

    float* xn2_p;
    unsigned short *xn1b_p, *xn2b_p, *w1b_p, *w2b_p;
    cudaGetSymbolAddress((void**)&xn2_p, g_xn2);
    cudaGetSymbolAddress((void**)&xn1b_p, g_xn1b);
    cudaGetSymbolAddress((void**)&xn2b_p, g_xn2b);
    cudaGetSymbolAddress((void**)&w1b_p, g_w1b);
    cudaGetSymbolAddress((void**)&w2b_p, g_w2b);

    const int BG_SMEM = (4 * 5120 + 4 * 4352) * 2;  // 75776 B (4-stage)
    cudaFuncSetAttribute(bgemm<1>, cudaFuncAttributeMaxDynamicSharedMemorySize, BG_SMEM);
    cudaFuncSetAttribute(bgemm<2>, cudaFuncAttributeMaxDynamicSharedMemorySize, BG_SMEM);
    cudaFuncSetAttribute(bgemm<3>, cudaFuncAttributeMaxDynamicSharedMemorySize, BG_SMEM);
    cudaFuncSetAttribute(bgemm<4>, cudaFuncAttributeMaxDynamicSharedMemorySize, BG_SMEM);

    zero_cnt_kernel<<<1, 32>>>();
    cvt_qkvo_kernel<<<dim3(576, 4), 256>>>(Wq, Wk, Wv, Wo);
    cvt_moe_kernel<<<2 * 9216, 256>>>(W1, W2, w1b_p, w2b_p);

    ln_kernel<<<TOKENS, 192>>>(x, ln1_g, ln1_b, nullptr, xn1b_p);

    // fused QKV (bf16 out)
    bgemm<4><<<dim3(18, TOKENS / 128), 256, BG_SMEM>>>(nullptr, nullptr, nullptr, DM, DM);

    // split-KV flash: 768 CTAs, then combine
    flash_attn_kernel<<<dim3(16, BH, 2), 128>>>();
    flash_combine_kernel<<<dim3(16, BH), 256>>>();

    // h = x + attn @ Wo + bo -> d_out (fp32)
    bgemm<1><<<dim3(DM / 128, TOKENS / 128), 256, BG_SMEM>>>(bo, x, out, DM, DM);

    ln_kernel<<<TOKENS, 192>>>(out, ln2_g, ln2_b, xn2_p, xn2b_p);

    router_kernel<<<TOKENS, 64>>>(Wr, br);
    offsets_kernel<<<1, 32>>>();
    scatter_kernel<<<(NSLOTS + 255) / 256, 256>>>();

    bgemm<2><<<dim3(DFF / 128, TOKENS / 128, NEXP), 256, BG_SMEM>>>(b1, nullptr, nullptr, DFF, DM);
    bgemm<3><<<dim3(DM / 128, TOKENS / 128, NEXP), 256, BG_SMEM>>>(b2, nullptr, out, DM, DFF);
}

// round 16
// speedup vs baseline: 1.1618x; 1.0564x over previous
#include <cuda_runtime.h>
#include <cuda_bf16.h>
#include <cuda_fp16.h>
#include <stdint.h>
#include <stddef.h>
#include <math.h>

#define TOKENS 2048
#define DM 768
#define DFF 3072
#define NEXP 8
#define SEQ 1024
#define NH 12
#define BH 24
#define HD 64
#define NSLOTS (2 * TOKENS)

// ---------------- scratch (static device globals; no allocations) ----------------
__device__ __align__(16) unsigned short g_xn1b[TOKENS * DM];
__device__ __align__(16) float          g_xn2[TOKENS * DM];
__device__ __align__(16) unsigned short g_xn2b[TOKENS * DM];
__device__ __align__(16) unsigned short g_qb[TOKENS * DM];
__device__ __align__(16) unsigned short g_kb[TOKENS * DM];
__device__ __align__(16) unsigned short g_vb[TOKENS * DM];
__device__ __align__(16) unsigned short g_attnb[TOKENS * DM];
__device__ __align__(16) unsigned short g_hbuf[(size_t)NSLOTS * DFF];
// split-KV flash partials
__device__ __align__(16) float  g_po[(size_t)2 * BH * 16 * 64 * 64];   // 12.6 MB
__device__ __align__(16) float2 g_pml[(size_t)2 * BH * SEQ];
// bf16 weights
__device__ __align__(16) unsigned short g_wqb[DM * DM];
__device__ __align__(16) unsigned short g_wkb[DM * DM];
__device__ __align__(16) unsigned short g_wvb[DM * DM];
__device__ __align__(16) unsigned short g_wob[DM * DM];
__device__ __align__(16) unsigned short g_w1b[(size_t)NEXP * DM * DFF];
__device__ __align__(16) unsigned short g_w2b[(size_t)NEXP * DFF * DM];
// routing
__device__ int   g_cnt[NEXP];
__device__ int   g_off[NEXP];
__device__ int   g_fill[NEXP];
__device__ int   g_top_e[NSLOTS];
__device__ float g_top_g[NSLOTS];
__device__ int   g_slot_tok[NSLOTS];
__device__ float g_slot_gate[NSLOTS];

// ---------------- helpers ----------------
__global__ void zero_cnt_kernel() {
    int t = threadIdx.x;
    if (t < NEXP) { g_cnt[t] = 0; g_fill[t] = 0; }
}

__device__ __forceinline__ uint32_t smem_u32(const void* p) {
    return (uint32_t)__cvta_generic_to_shared(p);
}
__device__ __forceinline__ uint32_t packbf(float x, float y) {
    __nv_bfloat162 h = __floats2bfloat162_rn(x, y);
    return *(uint32_t*)&h;
}
__device__ __forceinline__ void cp16(uint32_t saddr, const void* g) {
    asm volatile("cp.async.cg.shared.global [%0], [%1], 16;" :: "r"(saddr), "l"(g));
}
__device__ __forceinline__ void cp16z(uint32_t saddr, const void* g, int sz) {
    asm volatile("cp.async.cg.shared.global [%0], [%1], 16, %2;" :: "r"(saddr), "l"(g), "r"(sz));
}
#define CP_COMMIT() asm volatile("cp.async.commit_group;")
#define CP_WAIT(N)  asm volatile("cp.async.wait_group %0;" :: "n"(N))

__device__ __forceinline__ void ldsm_x4(uint32_t& r0, uint32_t& r1, uint32_t& r2, uint32_t& r3, uint32_t addr) {
    asm volatile("ldmatrix.sync.aligned.m8n8.x4.shared.b16 {%0,%1,%2,%3}, [%4];"
                 : "=r"(r0), "=r"(r1), "=r"(r2), "=r"(r3) : "r"(addr));
}
__device__ __forceinline__ void ldsm_x4_t(uint32_t& r0, uint32_t& r1, uint32_t& r2, uint32_t& r3, uint32_t addr) {
    asm volatile("ldmatrix.sync.aligned.m8n8.x4.trans.shared.b16 {%0,%1,%2,%3}, [%4];"
                 : "=r"(r0), "=r"(r1), "=r"(r2), "=r"(r3) : "r"(addr));
}
__device__ __forceinline__ void mma_bf16(float* c, uint32_t a0, uint32_t a1, uint32_t a2, uint32_t a3,
                                         uint32_t b0, uint32_t b1) {
    asm volatile("mma.sync.aligned.m16n8k16.row.col.f32.bf16.bf16.f32 "
                 "{%0,%1,%2,%3},{%4,%5,%6,%7},{%8,%9},{%0,%1,%2,%3};"
                 : "+f"(c[0]), "+f"(c[1]), "+f"(c[2]), "+f"(c[3])
                 : "r"(a0), "r"(a1), "r"(a2), "r"(a3), "r"(b0), "r"(b1));
}
__device__ __forceinline__ uint32_t ex2_f16x2(uint32_t a) {
    uint32_t r;
    asm volatile("ex2.approx.f16x2 %0, %1;" : "=r"(r) : "r"(a));
    return r;
}
__device__ __forceinline__ float gelu_exact(float x) {
    return 0.5f * x * (1.0f + erff(x * 0.70710678118654752f));
}

// ---------------- merged weight conversion (fp32 -> bf16), ONE launch ------------
__global__ void cvt_all_kernel(const float* __restrict__ Wq, const float* __restrict__ Wk,
                               const float* __restrict__ Wv, const float* __restrict__ Wo,
                               const float* __restrict__ W1, const float* __restrict__ W2,
                               unsigned short* __restrict__ d1, unsigned short* __restrict__ d2) {
    const size_t U_M = (size_t)DM * DM / 8;           // 73728 per qkvo matrix
    const size_t U_W = (size_t)NEXP * DM * DFF / 8;   // 2359296 per moe tensor
    size_t t = (size_t)blockIdx.x * 256 + threadIdx.x;
    const float* src;
    unsigned short* dst;
    if (t < 4 * U_M) {
        int seg = (int)(t / U_M);
        size_t u = t - (size_t)seg * U_M;
        src = (seg == 0) ? Wq : (seg == 1) ? Wk : (seg == 2) ? Wv : Wo;
        dst = (seg == 0) ? g_wqb : (seg == 1) ? g_wkb : (seg == 2) ? g_wvb : g_wob;
        t = u;
    } else {
        t -= 4 * U_M;
        if (t < U_W) { src = W1; dst = d1; }
        else         { src = W2; dst = d2; t -= U_W; }
    }
    size_t i = t * 8;
    float4 a = *(const float4*)(src + i);
    float4 b = *(const float4*)(src + i + 4);
    *(uint4*)(dst + i) = make_uint4(packbf(a.x, a.y), packbf(a.z, a.w),
                                    packbf(b.x, b.y), packbf(b.z, b.w));
}

// ---------------- bf16 GEMM, cp.async 4-stage pipeline ----------------
// MODE 1: out = attnb @ Wo + bo + x          (fp32 out)
// MODE 2: hbuf = gelu(gather(xn2b) @ W1[e] + b1[e])
// MODE 3: out[tok] += gate * (hbuf @ W2[e] + b2[e])   (atomic; SPLIT-K x2 on z)
// MODE 4: {qb,kb,vb} = xn1b @ {Wq,Wk,Wv}     (bf16 out)
#define AS_EL(S, R, Cc) sm[(S) * 5120 + (R) * 40 + (Cc)]
#define BS_EL(S, R, Cc) sm[20480 + (S) * 4352 + (R) * 136 + (Cc)]

template<int MODE>
__global__ __launch_bounds__(256)
void bgemm(const float* __restrict__ bias, const float* __restrict__ res,
           float* __restrict__ C, int N, int Kdim) {
    extern __shared__ unsigned short sm[];
    int e = 0, kchunk = 0;
    if (MODE == 2) e = blockIdx.z;
    if (MODE == 3) { e = blockIdx.z >> 1; kchunk = blockIdx.z & 1; }
    int cnt = 0, off = 0;
    if (MODE == 2 || MODE == 3) {
        cnt = g_cnt[e];
        off = g_off[e];
        if ((int)blockIdx.y * 128 >= cnt) return;
    }
    int Kloc = (MODE == 3) ? (Kdim >> 1) : Kdim;  // K range this CTA covers
    int kc0 = kchunk * Kloc;

    const unsigned short* Bp;
    unsigned short* outp16 = nullptr;
    int m00 = blockIdx.y * 128;
    int col0 = blockIdx.x * 128;
    if (MODE == 1)      Bp = g_wob;
    else if (MODE == 2) Bp = g_w1b + (size_t)e * DM * DFF;
    else if (MODE == 3) Bp = g_w2b + (size_t)e * DFF * DM;
    else {
        int seg = blockIdx.x / 6;
        Bp = (seg == 0) ? g_wqb : (seg == 1) ? g_wkb : g_wvb;
        outp16 = (seg == 0) ? g_qb : (seg == 1) ? g_kb : g_vb;
        col0 = (blockIdx.x % 6) * 128;
    }

    int tid = threadIdx.x, lane = tid & 31, warp = tid >> 5;
    int wm = (warp & 1) * 64, wn = (warp >> 1) * 32;
    int ar = tid >> 1, akc = (tid & 1) * 16;
    int bkr = tid >> 3, bc = (tid & 7) * 16;

    const unsigned short* abase;
    int azf = 16;
    if (MODE == 4)      abase = g_xn1b + (size_t)(m00 + ar) * DM;
    else if (MODE == 1) abase = g_attnb + (size_t)(m00 + ar) * DM;
    else if (MODE == 2) {
        int rc = m00 + ar;
        if (rc < cnt) abase = g_xn2b + (size_t)g_slot_tok[off + rc] * DM;
        else { abase = g_xn2b; azf = 0; }
    } else {
        int rc = m00 + ar;
        if (rc < cnt) abase = g_hbuf + (size_t)(off + rc) * DFF + kc0;
        else { abase = g_hbuf; azf = 0; }
    }
    const unsigned short* bbase = Bp + (size_t)(kc0 + bkr) * N + col0 + bc;

#define ISSUE_TILE(S, K0)                                                   \
    do {                                                                    \
        uint32_t da = smem_u32(&AS_EL(S, ar, akc));                         \
        cp16z(da, abase + (K0) + akc, azf);                                 \
        cp16z(da + 16, abase + (K0) + akc + 8, azf);                        \
        uint32_t db = smem_u32(&BS_EL(S, bkr, bc));                         \
        const unsigned short* bs_ = bbase + (size_t)(K0) * N;               \
        cp16(db, bs_);                                                      \
        cp16(db + 16, bs_ + 8);                                             \
    } while (0)

    int nIter = Kloc >> 5;
    ISSUE_TILE(0, 0);  CP_COMMIT();
    ISSUE_TILE(1, 32); CP_COMMIT();
    ISSUE_TILE(2, 64); CP_COMMIT();

    float acc[4][4][4] = {};

    for (int it = 0; it < nIter; it++) {
        int stage = it & 3;
        CP_WAIT(2);
        __syncthreads();
        {
            int nt = it + 3;
            if (nt < nIter) ISSUE_TILE(nt & 3, nt << 5);
            CP_COMMIT();
        }
#pragma unroll
        for (int ks = 0; ks < 2; ks++) {
            int kk = ks * 16;
            uint32_t a[4][4];
#pragma unroll
            for (int mi = 0; mi < 4; mi++) {
                uint32_t addr = smem_u32(&AS_EL(stage, wm + mi * 16 + (lane & 15), kk + (lane >> 4) * 8));
                ldsm_x4(a[mi][0], a[mi][1], a[mi][2], a[mi][3], addr);
            }
            uint32_t b[4][2];
#pragma unroll
            for (int nb = 0; nb < 2; nb++) {
                uint32_t addr = smem_u32(&BS_EL(stage, kk + (lane & 15), wn + nb * 16 + (lane >> 4) * 8));
                ldsm_x4_t(b[nb * 2][0], b[nb * 2][1], b[nb * 2 + 1][0], b[nb * 2 + 1][1], addr);
            }
#pragma unroll
            for (int mi = 0; mi < 4; mi++)
#pragma unroll
                for (int nj = 0; nj < 4; nj++)
                    mma_bf16(acc[mi][nj], a[mi][0], a[mi][1], a[mi][2], a[mi][3],
                             b[nj][0], b[nj][1]);
        }
        __syncthreads();
    }
#undef ISSUE_TILE

    int g = lane >> 2, t4 = lane & 3;
#pragma unroll
    for (int mi = 0; mi < 4; mi++) {
#pragma unroll
        for (int h2 = 0; h2 < 2; h2++) {
            int rloc = wm + mi * 16 + g + h2 * 8;
            if (MODE == 2 || MODE == 3) {
                int rc = m00 + rloc;
                if (rc >= cnt) continue;
                int slot = off + rc;
                if (MODE == 2) {
                    size_t base = (size_t)slot * DFF;
#pragma unroll
                    for (int nj = 0; nj < 4; nj++) {
                        int col = col0 + wn + nj * 8 + 2 * t4;
                        float v0 = gelu_exact(acc[mi][nj][h2 * 2 + 0] + bias[(size_t)e * DFF + col]);
                        float v1 = gelu_exact(acc[mi][nj][h2 * 2 + 1] + bias[(size_t)e * DFF + col + 1]);
                        *(uint32_t*)&g_hbuf[base + col] = packbf(v0, v1);
                    }
                } else {
                    int tok = g_slot_tok[slot];
                    float gt = g_slot_gate[slot];
#pragma unroll
                    for (int nj = 0; nj < 4; nj++) {
                        int col = col0 + wn + nj * 8 + 2 * t4;
                        float b0 = (kchunk == 0) ? bias[(size_t)e * DM + col]     : 0.f;
                        float b1 = (kchunk == 0) ? bias[(size_t)e * DM + col + 1] : 0.f;
                        float v0 = (acc[mi][nj][h2 * 2 + 0] + b0) * gt;
                        float v1 = (acc[mi][nj][h2 * 2 + 1] + b1) * gt;
                        atomicAdd(&C[(size_t)tok * DM + col], v0);
                        atomicAdd(&C[(size_t)tok * DM + col + 1], v1);
                    }
                }
            } else if (MODE == 1) {
                int row = m00 + rloc;
#pragma unroll
                for (int nj = 0; nj < 4; nj++) {
                    int col = col0 + wn + nj * 8 + 2 * t4;
                    float v0 = acc[mi][nj][h2 * 2 + 0] + bias[col] + res[(size_t)row * N + col];
                    float v1 = acc[mi][nj][h2 * 2 + 1] + bias[col + 1] + res[(size_t)row * N + col + 1];
                    *(float2*)&C[(size_t)row * N + col] = make_float2(v0, v1);
                }
            } else {
                int row = m00 + rloc;
#pragma unroll
                for (int nj = 0; nj < 4; nj++) {
                    int col = col0 + wn + nj * 8 + 2 * t4;
                    *(uint32_t*)&outp16[(size_t)row * DM + col] =
                        packbf(acc[mi][nj][h2 * 2 + 0], acc[mi][nj][h2 * 2 + 1]);
                }
            }
        }
    }
}

// ---------------- split-KV flash attention: grid (16, BH, 2) --------------------
__global__ __launch_bounds__(128)
void flash_attn_kernel() {
    int bh = blockIdx.y; int b = bh / NH, h = bh % NH;
    int qt = 15 - (int)blockIdx.x;
    int q0 = qt * 64;
    int chunk = blockIdx.z;
    int nkv = qt + 1;
    int mid = (nkv + 1) >> 1;
    int kt0 = (chunk == 0) ? 0 : mid;
    int kt1 = (chunk == 0) ? mid : nkv;
    int tid = threadIdx.x, lane = tid & 31, warp = tid >> 5;
    int wq = warp * 16;

    float2* pml = g_pml + ((size_t)chunk * BH + bh) * SEQ + q0;
    if (kt0 >= kt1) {
        if (tid < 64) pml[tid] = make_float2(-1e30f, 0.f);
        return;
    }

    __shared__ unsigned short Qs[64][72];
    __shared__ unsigned short Ks[2][64][72];
    __shared__ unsigned short Vs[2][64][72];

    int lr = tid >> 1, lc = (tid & 1) * 32;

#define FA_ISSUE(BUF, K0)                                                          \
    do {                                                                           \
        const unsigned short* kp = g_kb + (size_t)(b * SEQ + (K0) + lr) * DM + h * HD + lc; \
        const unsigned short* vp = g_vb + (size_t)(b * SEQ + (K0) + lr) * DM + h * HD + lc; \
        uint32_t ka = smem_u32(&Ks[BUF][lr][lc]);                                  \
        uint32_t va = smem_u32(&Vs[BUF][lr][lc]);                                  \
        cp16(ka, kp); cp16(ka + 16, kp + 8); cp16(ka + 32, kp + 16); cp16(ka + 48, kp + 24); \
        cp16(va, vp); cp16(va + 16, vp + 8); cp16(va + 32, vp + 16); cp16(va + 48, vp + 24); \
    } while (0)

    FA_ISSUE(0, kt0 * 64);
    CP_COMMIT();

    {
        const unsigned short* qp = g_qb + (size_t)(b * SEQ + q0 + lr) * DM + h * HD + lc;
        *(uint4*)&Qs[lr][lc]      = *(const uint4*)(qp);
        *(uint4*)&Qs[lr][lc + 8]  = *(const uint4*)(qp + 8);
        *(uint4*)&Qs[lr][lc + 16] = *(const uint4*)(qp + 16);
        *(uint4*)&Qs[lr][lc + 24] = *(const uint4*)(qp + 24);
    }
    __syncthreads();

    uint32_t qa[4][4];
#pragma unroll
    for (int kc = 0; kc < 4; kc++) {
        uint32_t addr = smem_u32(&Qs[wq + (lane & 15)][kc * 16 + (lane >> 4) * 8]);
        ldsm_x4(qa[kc][0], qa[kc][1], qa[kc][2], qa[kc][3], addr);
    }

    float m_run[2] = {-1e30f, -1e30f};
    float l_run[2] = {0.f, 0.f};
    float oacc[8][4] = {};

    for (int kt = kt0; kt < kt1; kt++) {
        int k0 = kt * 64;
        int buf = (kt - kt0) & 1;
        CP_WAIT(0);
        __syncthreads();
        if (kt + 1 < kt1) { FA_ISSUE(buf ^ 1, k0 + 64); CP_COMMIT(); }

        float sacc[8][4] = {};
#pragma unroll
        for (int kc = 0; kc < 4; kc++) {
#pragma unroll
            for (int nb = 0; nb < 4; nb++) {
                uint32_t r0, r1, r2, r3;
                uint32_t addr = smem_u32(&Ks[buf][nb * 16 + (lane & 7) + ((lane >> 3) & 1) * 8]
                                            [kc * 16 + (lane >> 4) * 8]);
                ldsm_x4(r0, r1, r2, r3, addr);
                mma_bf16(sacc[nb * 2],     qa[kc][0], qa[kc][1], qa[kc][2], qa[kc][3], r0, r2);
                mma_bf16(sacc[nb * 2 + 1], qa[kc][0], qa[kc][1], qa[kc][2], qa[kc][3], r1, r3);
            }
        }

        bool diag = (kt == qt);
#pragma unroll
        for (int half = 0; half < 2; half++) {
            int qrow = q0 + wq + (lane >> 2) + half * 8;
            float vals[16];
#pragma unroll
            for (int nj = 0; nj < 8; nj++) {
                int colg = k0 + nj * 8 + 2 * (lane & 3);
                float v0 = sacc[nj][half * 2 + 0] * 0.125f;
                float v1 = sacc[nj][half * 2 + 1] * 0.125f;
                if (diag) {
                    if (colg > qrow) v0 = -1e30f;
                    if (colg + 1 > qrow) v1 = -1e30f;
                }
                vals[nj * 2] = v0;
                vals[nj * 2 + 1] = v1;
            }
            float tmx = vals[0];
#pragma unroll
            for (int i = 1; i < 16; i++) tmx = fmaxf(tmx, vals[i]);
            tmx = fmaxf(tmx, __shfl_xor_sync(0xffffffffu, tmx, 1));
            tmx = fmaxf(tmx, __shfl_xor_sync(0xffffffffu, tmx, 2));
            float mnew = fmaxf(m_run[half], tmx);
            float corr = __expf(m_run[half] - mnew);
            float rsum = 0.f;
#pragma unroll
            for (int i = 0; i < 8; i++) {
                float t0 = (vals[2 * i + 0] - mnew) * 1.44269504f;
                float t1 = (vals[2 * i + 1] - mnew) * 1.44269504f;
                __half2 ht = __floats2half2_rn(t0, t1);
                uint32_t pb = ex2_f16x2(*(uint32_t*)&ht);
                float2 p = __half22float2(*(__half2*)&pb);
                vals[2 * i + 0] = p.x;
                vals[2 * i + 1] = p.y;
                rsum += p.x + p.y;
            }
            rsum += __shfl_xor_sync(0xffffffffu, rsum, 1);
            rsum += __shfl_xor_sync(0xffffffffu, rsum, 2);
            l_run[half] = l_run[half] * corr + rsum;
            m_run[half] = mnew;
#pragma unroll
            for (int nj = 0; nj < 8; nj++) {
                oacc[nj][half * 2 + 0] *= corr;
                oacc[nj][half * 2 + 1] *= corr;
                sacc[nj][half * 2 + 0] = vals[nj * 2];
                sacc[nj][half * 2 + 1] = vals[nj * 2 + 1];
            }
        }

#pragma unroll
        for (int j = 0; j < 4; j++) {
            uint32_t pa0 = packbf(sacc[2 * j][0], sacc[2 * j][1]);
            uint32_t pa1 = packbf(sacc[2 * j][2], sacc[2 * j][3]);
            uint32_t pa2 = packbf(sacc[2 * j + 1][0], sacc[2 * j + 1][1]);
            uint32_t pa3 = packbf(sacc[2 * j + 1][2], sacc[2 * j + 1][3]);
#pragma unroll
            for (int nb = 0; nb < 2; nb++) {
                uint32_t b0, b1, b2, b3;
                uint32_t addr = smem_u32(&Vs[buf][j * 16 + (lane & 15)][nb * 32 + (lane >> 4) * 8]);
                ldsm_x4_t(b0, b1, b2, b3, addr);
                mma_bf16(oacc[nb * 4 + 0], pa0, pa1, pa2, pa3, b0, b1);
                mma_bf16(oacc[nb * 4 + 1], pa0, pa1, pa2, pa3, b2, b3);
                addr = smem_u32(&Vs[buf][j * 16 + (lane & 15)][nb * 32 + 16 + (lane >> 4) * 8]);
                ldsm_x4_t(b0, b1, b2, b3, addr);
                mma_bf16(oacc[nb * 4 + 2], pa0, pa1, pa2, pa3, b0, b1);
                mma_bf16(oacc[nb * 4 + 3], pa0, pa1, pa2, pa3, b2, b3);
            }
        }
    }
#undef FA_ISSUE

    float* po = g_po + (((size_t)chunk * BH + bh) * 16 + (size_t)qt) * 4096;
#pragma unroll
    for (int half = 0; half < 2; half++) {
        int rloc = wq + (lane >> 2) + half * 8;
        if ((lane & 3) == 0) pml[rloc] = make_float2(m_run[half], l_run[half]);
#pragma unroll
        for (int nj = 0; nj < 8; nj++) {
            int col = nj * 8 + 2 * (lane & 3);
            *(float2*)&po[rloc * 64 + col] =
                make_float2(oacc[nj][half * 2 + 0], oacc[nj][half * 2 + 1]);
        }
    }
}

// ---------------- flash combine ----------------
__global__ __launch_bounds__(256)
void flash_combine_kernel() {
    int qt = blockIdx.x, bh = blockIdx.y;
    int b = bh / NH, h = bh % NH;
    int q0 = qt * 64;
    int tid = threadIdx.x;
    int r = tid >> 2, cseg = (tid & 3) * 16;

    float2 ml0 = g_pml[((size_t)0 * BH + bh) * SEQ + q0 + r];
    float2 ml1 = g_pml[((size_t)1 * BH + bh) * SEQ + q0 + r];
    bool v1 = ml1.y > 0.f;
    float mstar = fmaxf(ml0.x, v1 ? ml1.x : -1e30f);
    float e0 = __expf(ml0.x - mstar);
    float e1 = v1 ? __expf(ml1.x - mstar) : 0.f;
    float inv = 1.0f / (ml0.y * e0 + (v1 ? ml1.y * e1 : 0.f));

    const float* po0 = g_po + (((size_t)0 * BH + bh) * 16 + (size_t)qt) * 4096 + r * 64;
    const float* po1 = g_po + (((size_t)1 * BH + bh) * 16 + (size_t)qt) * 4096 + r * 64;
    unsigned short* dst = g_attnb + (size_t)(b * SEQ + q0 + r) * DM + h * HD;
#pragma unroll
    for (int i = 0; i < 4; i++) {
        int col = cseg + i * 4;
        float4 o0 = *(const float4*)(po0 + col);
        float4 o1 = v1 ? *(const float4*)(po1 + col) : make_float4(0.f, 0.f, 0.f, 0.f);
        float vx = (o0.x * e0 + o1.x * e1) * inv;
        float vy = (o0.y * e0 + o1.y * e1) * inv;
        float vz = (o0.z * e0 + o1.z * e1) * inv;
        float vw = (o0.w * e0 + o1.w * e1) * inv;
        *(uint2*)&dst[col] = make_uint2(packbf(vx, vy), packbf(vz, vw));
    }
}

// ---------------- layernorm: 192 threads, float4, single-pass sum/sumsq ---------
__global__ __launch_bounds__(192)
void ln_kernel(const float* __restrict__ x, const float* __restrict__ gam,
               const float* __restrict__ bet, float* __restrict__ yf,
               unsigned short* __restrict__ yb) {
    int row = blockIdx.x;
    int tid = threadIdx.x;  // 192 = DM/4
    __shared__ float rs[6], rs2[6];
    float4 v = ((const float4*)(x + (size_t)row * DM))[tid];
    float s  = v.x + v.y + v.z + v.w;
    float s2 = v.x * v.x + v.y * v.y + v.z * v.z + v.w * v.w;
#pragma unroll
    for (int o = 16; o > 0; o >>= 1) {
        s  += __shfl_xor_sync(0xffffffffu, s,  o);
        s2 += __shfl_xor_sync(0xffffffffu, s2, o);
    }
    if ((tid & 31) == 0) { rs[tid >> 5] = s; rs2[tid >> 5] = s2; }
    __syncthreads();
    float ts = 0.f, ts2 = 0.f;
#pragma unroll
    for (int i = 0; i < 6; i++) { ts += rs[i]; ts2 += rs2[i]; }
    float m = ts * (1.0f / DM);
    float var = ts2 * (1.0f / DM) - m * m;
    float r = rsqrtf(var + 1e-5f);
    float4 g4 = ((const float4*)gam)[tid];
    float4 b4 = ((const float4*)bet)[tid];
    float4 o4;
    o4.x = (v.x - m) * r * g4.x + b4.x;
    o4.y = (v.y - m) * r * g4.y + b4.y;
    o4.z = (v.z - m) * r * g4.z + b4.z;
    o4.w = (v.w - m) * r * g4.w + b4.w;
    if (yf) ((float4*)(yf + (size_t)row * DM))[tid] = o4;
    *(uint2*)(yb + (size_t)row * DM + tid * 4) =
        make_uint2(packbf(o4.x, o4.y), packbf(o4.z, o4.w));
}

// ---------------- router ----------------
__global__ void router_kernel(const float* __restrict__ Wr, const float* __restrict__ br) {
    int t = blockIdx.x, tid = threadIdx.x;  // 64 threads
    float acc[NEXP] = {};
    const float* xr = g_xn2 + (size_t)t * DM;
    for (int d = tid; d < DM; d += 64) {
        float xv = xr[d];
        const float* w = Wr + (size_t)d * NEXP;
#pragma unroll
        for (int e = 0; e < NEXP; e++) acc[e] += xv * w[e];
    }
    __shared__ float sh[64][NEXP + 1];
#pragma unroll
    for (int e = 0; e < NEXP; e++) sh[tid][e] = acc[e];
    __syncthreads();
    if (tid < NEXP) {
        float s = br[tid];
        for (int i = 0; i < 64; i++) s += sh[i][tid];
        sh[0][tid] = s;
    }
    __syncthreads();
    if (tid == 0) {
        float l[NEXP];
#pragma unroll
        for (int e = 0; e < NEXP; e++) l[e] = sh[0][e];
        int i1 = 0;
        for (int e = 1; e < NEXP; e++) if (l[e] > l[i1]) i1 = e;
        int i2 = (i1 == 0) ? 1 : 0;
        for (int e = 0; e < NEXP; e++) if (e != i1 && l[e] > l[i2]) i2 = e;
        float g1 = 1.0f / (1.0f + expf(l[i2] - l[i1]));
        float g2 = 1.0f - g1;
        g_top_e[2 * t] = i1; g_top_g[2 * t] = g1;
        g_top_e[2 * t + 1] = i2; g_top_g[2 * t + 1] = g2;
        atomicAdd(&g_cnt[i1], 1);
        atomicAdd(&g_cnt[i2], 1);
    }
}

__global__ void offsets_kernel() {
    if (threadIdx.x == 0) {
        int acc = 0;
#pragma unroll
        for (int e = 0; e < NEXP; e++) { g_off[e] = acc; acc += g_cnt[e]; }
    }
}

__global__ void scatter_kernel() {
    int i = blockIdx.x * 256 + threadIdx.x;
    if (i >= NSLOTS) return;
    int e = g_top_e[i];
    int p = atomicAdd(&g_fill[e], 1);
    int slot = g_off[e] + p;
    g_slot_tok[slot] = i >> 1;
    g_slot_gate[slot] = g_top_g[i];
}

// ---------------- launch ----------------
extern "C" void kernel_launch(void* const* d_in, const int* in_sizes, int n_in,
                              void* d_out, int out_size) {
    const float* x     = (const float*)d_in[0];
    const float* ln1_g = (const float*)d_in[1];
    const float* ln1_b = (const float*)d_in[2];
    const float* Wq    = (const float*)d_in[3];
    const float* Wk    = (const float*)d_in[4];
    const float* Wv    = (const float*)d_in[5];
    const float* Wo    = (const float*)d_in[6];
    const float* bo    = (const float*)d_in[7];
    const float* ln2_g = (const float*)d_in[8];
    const float* ln2_b = (const float*)d_in[9];
    const float* Wr    = (const float*)d_in[10];
    const float* br    = (const float*)d_in[11];
    const float* W1    = (const float*)d_in[12];
    const float* b1    = (const float*)d_in[13];
    const float* W2    = (const float*)d_in[14];
    const float* b2    = (const float*)d_in[15];
    float* out = (float*)d_out;

    float* xn2_p;
    unsigned short *xn1b_p, *xn2b_p, *w1b_p, *w2b_p;
    cudaGetSymbolAddress((void**)&xn2_p, g_xn2);
    cudaGetSymbolAddress((void**)&xn1b_p, g_xn1b);
    cudaGetSymbolAddress((void**)&xn2b_p, g_xn2b);
    cudaGetSymbolAddress((void**)&w1b_p, g_w1b);
    cudaGetSymbolAddress((void**)&w2b_p, g_w2b);

    const int BG_SMEM = (4 * 5120 + 4 * 4352) * 2;  // 75776 B (4-stage)
    cudaFuncSetAttribute(bgemm<1>, cudaFuncAttributeMaxDynamicSharedMemorySize, BG_SMEM);
    cudaFuncSetAttribute(bgemm<2>, cudaFuncAttributeMaxDynamicSharedMemorySize, BG_SMEM);
    cudaFuncSetAttribute(bgemm<3>, cudaFuncAttributeMaxDynamicSharedMemorySize, BG_SMEM);
    cudaFuncSetAttribute(bgemm<4>, cudaFuncAttributeMaxDynamicSharedMemorySize, BG_SMEM);

    zero_cnt_kernel<<<1, 32>>>();
    // ALL weight conversions in one launch
    {
        const size_t total = 4 * ((size_t)DM * DM / 8) + 2 * ((size_t)NEXP * DM * DFF / 8);
        cvt_all_kernel<<<(unsigned)((total + 255) / 256), 256>>>(Wq, Wk, Wv, Wo, W1, W2, w1b_p, w2b_p);
    }

    ln_kernel<<<TOKENS, 192>>>(x, ln1_g, ln1_b, nullptr, xn1b_p);

    // fused QKV (bf16 out)
    bgemm<4><<<dim3(18, TOKENS / 128), 256, BG_SMEM>>>(nullptr, nullptr, nullptr, DM, DM);

    // split-KV flash + combine
    flash_attn_kernel<<<dim3(16, BH, 2), 128>>>();
    flash_combine_kernel<<<dim3(16, BH), 256>>>();

    // h = x + attn @ Wo + bo -> d_out (fp32)
    bgemm<1><<<dim3(DM / 128, TOKENS / 128), 256, BG_SMEM>>>(bo, x, out, DM, DM);

    ln_kernel<<<TOKENS, 192>>>(out, ln2_g, ln2_b, xn2_p, xn2b_p);

    router_kernel<<<TOKENS, 64>>>(Wr, br);
    offsets_kernel<<<1, 32>>>();
    scatter_kernel<<<(NSLOTS + 255) / 256, 256>>>();

    bgemm<2><<<dim3(DFF / 128, TOKENS / 128, NEXP), 256, BG_SMEM>>>(b1, nullptr, nullptr, DFF, DM);
    // MoE GEMM2 with split-K x2: z = expert*2 + kchunk
    bgemm<3><<<dim3(DM / 128, TOKENS / 128, NEXP * 2), 256, BG_SMEM>>>(b2, nullptr, out, DM, DFF);
}

// round 17
// speedup vs baseline: 1.1765x; 1.0127x over previous
#include <cuda_runtime.h>
#include <cuda_bf16.h>
#include <cuda_fp16.h>
#include <stdint.h>
#include <stddef.h>
#include <math.h>

#define TOKENS 2048
#define DM 768
#define DFF 3072
#define NEXP 8
#define SEQ 1024
#define NH 12
#define BH 24
#define HD 64
#define NSLOTS (2 * TOKENS)

// ---------------- scratch (static device globals; no allocations) ----------------
__device__ __align__(16) unsigned short g_xn1b[TOKENS * DM];
__device__ __align__(16) float          g_xn2[TOKENS * DM];
__device__ __align__(16) unsigned short g_xn2b[TOKENS * DM];
__device__ __align__(16) unsigned short g_qb[TOKENS * DM];
__device__ __align__(16) unsigned short g_kb[TOKENS * DM];
__device__ __align__(16) unsigned short g_vb[TOKENS * DM];
__device__ __align__(16) unsigned short g_attnb[TOKENS * DM];
__device__ __align__(16) unsigned short g_hbuf[(size_t)NSLOTS * DFF];
// split-KV flash partials
__device__ __align__(16) float  g_po[(size_t)2 * BH * 16 * 64 * 64];   // 12.6 MB
__device__ __align__(16) float2 g_pml[(size_t)2 * BH * SEQ];
// bf16 weights
__device__ __align__(16) unsigned short g_wqb[DM * DM];
__device__ __align__(16) unsigned short g_wkb[DM * DM];
__device__ __align__(16) unsigned short g_wvb[DM * DM];
__device__ __align__(16) unsigned short g_wob[DM * DM];
__device__ __align__(16) unsigned short g_w1b[(size_t)NEXP * DM * DFF];
__device__ __align__(16) unsigned short g_w2b[(size_t)NEXP * DFF * DM];
// routing
__device__ int   g_cnt[NEXP];
__device__ int   g_off[NEXP];
__device__ int   g_fill[NEXP];
__device__ int   g_top_e[NSLOTS];
__device__ float g_top_g[NSLOTS];
__device__ int   g_slot_tok[NSLOTS];
__device__ float g_slot_gate[NSLOTS];

// ---------------- helpers ----------------
__global__ void zero_cnt_kernel() {
    int t = threadIdx.x;
    if (t < NEXP) { g_cnt[t] = 0; g_fill[t] = 0; }
}

__device__ __forceinline__ uint32_t smem_u32(const void* p) {
    return (uint32_t)__cvta_generic_to_shared(p);
}
__device__ __forceinline__ uint32_t packbf(float x, float y) {
    __nv_bfloat162 h = __floats2bfloat162_rn(x, y);
    return *(uint32_t*)&h;
}
__device__ __forceinline__ void cp16(uint32_t saddr, const void* g) {
    asm volatile("cp.async.cg.shared.global [%0], [%1], 16;" :: "r"(saddr), "l"(g));
}
__device__ __forceinline__ void cp16z(uint32_t saddr, const void* g, int sz) {
    asm volatile("cp.async.cg.shared.global [%0], [%1], 16, %2;" :: "r"(saddr), "l"(g), "r"(sz));
}
#define CP_COMMIT() asm volatile("cp.async.commit_group;")
#define CP_WAIT(N)  asm volatile("cp.async.wait_group %0;" :: "n"(N))

__device__ __forceinline__ void ldsm_x4(uint32_t& r0, uint32_t& r1, uint32_t& r2, uint32_t& r3, uint32_t addr) {
    asm volatile("ldmatrix.sync.aligned.m8n8.x4.shared.b16 {%0,%1,%2,%3}, [%4];"
                 : "=r"(r0), "=r"(r1), "=r"(r2), "=r"(r3) : "r"(addr));
}
__device__ __forceinline__ void ldsm_x4_t(uint32_t& r0, uint32_t& r1, uint32_t& r2, uint32_t& r3, uint32_t addr) {
    asm volatile("ldmatrix.sync.aligned.m8n8.x4.trans.shared.b16 {%0,%1,%2,%3}, [%4];"
                 : "=r"(r0), "=r"(r1), "=r"(r2), "=r"(r3) : "r"(addr));
}
__device__ __forceinline__ void mma_bf16(float* c, uint32_t a0, uint32_t a1, uint32_t a2, uint32_t a3,
                                         uint32_t b0, uint32_t b1) {
    asm volatile("mma.sync.aligned.m16n8k16.row.col.f32.bf16.bf16.f32 "
                 "{%0,%1,%2,%3},{%4,%5,%6,%7},{%8,%9},{%0,%1,%2,%3};"
                 : "+f"(c[0]), "+f"(c[1]), "+f"(c[2]), "+f"(c[3])
                 : "r"(a0), "r"(a1), "r"(a2), "r"(a3), "r"(b0), "r"(b1));
}
__device__ __forceinline__ uint32_t ex2_f16x2(uint32_t a) {
    uint32_t r;
    asm volatile("ex2.approx.f16x2 %0, %1;" : "=r"(r) : "r"(a));
    return r;
}
__device__ __forceinline__ float gelu_exact(float x) {
    return 0.5f * x * (1.0f + erff(x * 0.70710678118654752f));
}

// ---------------- merged weight conversion (fp32 -> bf16), ONE launch ------------
__global__ void cvt_all_kernel(const float* __restrict__ Wq, const float* __restrict__ Wk,
                               const float* __restrict__ Wv, const float* __restrict__ Wo,
                               const float* __restrict__ W1, const float* __restrict__ W2,
                               unsigned short* __restrict__ d1, unsigned short* __restrict__ d2) {
    const size_t U_M = (size_t)DM * DM / 8;
    const size_t U_W = (size_t)NEXP * DM * DFF / 8;
    size_t t = (size_t)blockIdx.x * 256 + threadIdx.x;
    const float* src;
    unsigned short* dst;
    if (t < 4 * U_M) {
        int seg = (int)(t / U_M);
        size_t u = t - (size_t)seg * U_M;
        src = (seg == 0) ? Wq : (seg == 1) ? Wk : (seg == 2) ? Wv : Wo;
        dst = (seg == 0) ? g_wqb : (seg == 1) ? g_wkb : (seg == 2) ? g_wvb : g_wob;
        t = u;
    } else {
        t -= 4 * U_M;
        if (t < U_W) { src = W1; dst = d1; }
        else         { src = W2; dst = d2; t -= U_W; }
    }
    size_t i = t * 8;
    float4 a = *(const float4*)(src + i);
    float4 b = *(const float4*)(src + i + 4);
    *(uint4*)(dst + i) = make_uint4(packbf(a.x, a.y), packbf(a.z, a.w),
                                    packbf(b.x, b.y), packbf(b.z, b.w));
}

// ---------------- bf16 GEMM, cp.async 4-stage pipeline, tile TM x 128 ------------
// MODE 1: out = attnb @ Wo + bo + x          (fp32 out)           [TM=64]
// MODE 2: hbuf = gelu(gather(xn2b) @ W1[e] + b1[e])               [TM=128]
// MODE 3: out[tok] += gate * (hbuf @ W2[e] + b2[e])  split-K x2   [TM=128]
// MODE 4: {qb,kb,vb} = xn1b @ {Wq,Wk,Wv}     (bf16 out)           [TM=64]
template<int MODE, int TM>
__global__ __launch_bounds__(256)
void bgemm(const float* __restrict__ bias, const float* __restrict__ res,
           float* __restrict__ C, int N, int Kdim) {
    extern __shared__ unsigned short sm[];
    constexpr int AST = TM * 40;          // A stage stride (elements)
    constexpr int BOFF = 4 * AST;         // B region offset
    constexpr int MI = TM / 32;           // warp-tile m-fragments

    int e = 0, kchunk = 0;
    if (MODE == 2) e = blockIdx.z;
    if (MODE == 3) { e = blockIdx.z >> 1; kchunk = blockIdx.z & 1; }
    int cnt = 0, off = 0;
    if (MODE == 2 || MODE == 3) {
        cnt = g_cnt[e];
        off = g_off[e];
        if ((int)blockIdx.y * TM >= cnt) return;
    }
    int Kloc = (MODE == 3) ? (Kdim >> 1) : Kdim;
    int kc0 = kchunk * Kloc;

    const unsigned short* Bp;
    unsigned short* outp16 = nullptr;
    int m00 = blockIdx.y * TM;
    int col0 = blockIdx.x * 128;
    if (MODE == 1)      Bp = g_wob;
    else if (MODE == 2) Bp = g_w1b + (size_t)e * DM * DFF;
    else if (MODE == 3) Bp = g_w2b + (size_t)e * DFF * DM;
    else {
        int seg = blockIdx.x / 6;
        Bp = (seg == 0) ? g_wqb : (seg == 1) ? g_wkb : g_wvb;
        outp16 = (seg == 0) ? g_qb : (seg == 1) ? g_kb : g_vb;
        col0 = (blockIdx.x % 6) * 128;
    }

    int tid = threadIdx.x, lane = tid & 31, warp = tid >> 5;
    int wm = (warp & 1) * (TM / 2), wn = (warp >> 1) * 32;
    // A loader mapping
    int ar, akc;
    if (TM == 128) { ar = tid >> 1; akc = (tid & 1) * 16; }
    else           { ar = tid >> 2; akc = (tid & 3) * 8;  }
    int bkr = tid >> 3, bc = (tid & 7) * 16;

    const unsigned short* abase;
    int azf = 16;
    if (MODE == 4)      abase = g_xn1b + (size_t)(m00 + ar) * DM;
    else if (MODE == 1) abase = g_attnb + (size_t)(m00 + ar) * DM;
    else if (MODE == 2) {
        int rc = m00 + ar;
        if (rc < cnt) abase = g_xn2b + (size_t)g_slot_tok[off + rc] * DM;
        else { abase = g_xn2b; azf = 0; }
    } else {
        int rc = m00 + ar;
        if (rc < cnt) abase = g_hbuf + (size_t)(off + rc) * DFF + kc0;
        else { abase = g_hbuf; azf = 0; }
    }
    const unsigned short* bbase = Bp + (size_t)(kc0 + bkr) * N + col0 + bc;

#define ISSUE_TILE(S, K0)                                                   \
    do {                                                                    \
        uint32_t da = smem_u32(&sm[(S) * AST + ar * 40 + akc]);             \
        cp16z(da, abase + (K0) + akc, azf);                                 \
        if (TM == 128) cp16z(da + 16, abase + (K0) + akc + 8, azf);         \
        uint32_t db = smem_u32(&sm[BOFF + (S) * 4352 + bkr * 136 + bc]);    \
        const unsigned short* bs_ = bbase + (size_t)(K0) * N;               \
        cp16(db, bs_);                                                      \
        cp16(db + 16, bs_ + 8);                                             \
    } while (0)

    int nIter = Kloc >> 5;
    ISSUE_TILE(0, 0);  CP_COMMIT();
    ISSUE_TILE(1, 32); CP_COMMIT();
    ISSUE_TILE(2, 64); CP_COMMIT();

    float acc[MI][4][4] = {};

    for (int it = 0; it < nIter; it++) {
        int stage = it & 3;
        CP_WAIT(2);
        __syncthreads();
        {
            int nt = it + 3;
            if (nt < nIter) ISSUE_TILE(nt & 3, nt << 5);
            CP_COMMIT();
        }
#pragma unroll
        for (int ks = 0; ks < 2; ks++) {
            int kk = ks * 16;
            uint32_t a[MI][4];
#pragma unroll
            for (int mi = 0; mi < MI; mi++) {
                uint32_t addr = smem_u32(&sm[stage * AST + (wm + mi * 16 + (lane & 15)) * 40
                                             + kk + (lane >> 4) * 8]);
                ldsm_x4(a[mi][0], a[mi][1], a[mi][2], a[mi][3], addr);
            }
            uint32_t b[4][2];
#pragma unroll
            for (int nb = 0; nb < 2; nb++) {
                uint32_t addr = smem_u32(&sm[BOFF + stage * 4352 + (kk + (lane & 15)) * 136
                                             + wn + nb * 16 + (lane >> 4) * 8]);
                ldsm_x4_t(b[nb * 2][0], b[nb * 2][1], b[nb * 2 + 1][0], b[nb * 2 + 1][1], addr);
            }
#pragma unroll
            for (int mi = 0; mi < MI; mi++)
#pragma unroll
                for (int nj = 0; nj < 4; nj++)
                    mma_bf16(acc[mi][nj], a[mi][0], a[mi][1], a[mi][2], a[mi][3],
                             b[nj][0], b[nj][1]);
        }
        __syncthreads();
    }
#undef ISSUE_TILE

    int g = lane >> 2, t4 = lane & 3;
#pragma unroll
    for (int mi = 0; mi < MI; mi++) {
#pragma unroll
        for (int h2 = 0; h2 < 2; h2++) {
            int rloc = wm + mi * 16 + g + h2 * 8;
            if (MODE == 2 || MODE == 3) {
                int rc = m00 + rloc;
                if (rc >= cnt) continue;
                int slot = off + rc;
                if (MODE == 2) {
                    size_t base = (size_t)slot * DFF;
#pragma unroll
                    for (int nj = 0; nj < 4; nj++) {
                        int col = col0 + wn + nj * 8 + 2 * t4;
                        float v0 = gelu_exact(acc[mi][nj][h2 * 2 + 0] + bias[(size_t)e * DFF + col]);
                        float v1 = gelu_exact(acc[mi][nj][h2 * 2 + 1] + bias[(size_t)e * DFF + col + 1]);
                        *(uint32_t*)&g_hbuf[base + col] = packbf(v0, v1);
                    }
                } else {
                    int tok = g_slot_tok[slot];
                    float gt = g_slot_gate[slot];
#pragma unroll
                    for (int nj = 0; nj < 4; nj++) {
                        int col = col0 + wn + nj * 8 + 2 * t4;
                        float b0 = (kchunk == 0) ? bias[(size_t)e * DM + col]     : 0.f;
                        float b1 = (kchunk == 0) ? bias[(size_t)e * DM + col + 1] : 0.f;
                        float v0 = (acc[mi][nj][h2 * 2 + 0] + b0) * gt;
                        float v1 = (acc[mi][nj][h2 * 2 + 1] + b1) * gt;
                        atomicAdd(&C[(size_t)tok * DM + col], v0);
                        atomicAdd(&C[(size_t)tok * DM + col + 1], v1);
                    }
                }
            } else if (MODE == 1) {
                int row = m00 + rloc;
#pragma unroll
                for (int nj = 0; nj < 4; nj++) {
                    int col = col0 + wn + nj * 8 + 2 * t4;
                    float v0 = acc[mi][nj][h2 * 2 + 0] + bias[col] + res[(size_t)row * N + col];
                    float v1 = acc[mi][nj][h2 * 2 + 1] + bias[col + 1] + res[(size_t)row * N + col + 1];
                    *(float2*)&C[(size_t)row * N + col] = make_float2(v0, v1);
                }
            } else {
                int row = m00 + rloc;
#pragma unroll
                for (int nj = 0; nj < 4; nj++) {
                    int col = col0 + wn + nj * 8 + 2 * t4;
                    *(uint32_t*)&outp16[(size_t)row * DM + col] =
                        packbf(acc[mi][nj][h2 * 2 + 0], acc[mi][nj][h2 * 2 + 1]);
                }
            }
        }
    }
}

// ---------------- split-KV flash attention: grid (16, BH, 2) --------------------
__global__ __launch_bounds__(128)
void flash_attn_kernel() {
    int bh = blockIdx.y; int b = bh / NH, h = bh % NH;
    int qt = 15 - (int)blockIdx.x;
    int q0 = qt * 64;
    int chunk = blockIdx.z;
    int nkv = qt + 1;
    int mid = (nkv + 1) >> 1;
    int kt0 = (chunk == 0) ? 0 : mid;
    int kt1 = (chunk == 0) ? mid : nkv;
    int tid = threadIdx.x, lane = tid & 31, warp = tid >> 5;
    int wq = warp * 16;

    float2* pml = g_pml + ((size_t)chunk * BH + bh) * SEQ + q0;
    if (kt0 >= kt1) {
        if (tid < 64) pml[tid] = make_float2(-1e30f, 0.f);
        return;
    }

    __shared__ unsigned short Qs[64][72];
    __shared__ unsigned short Ks[2][64][72];
    __shared__ unsigned short Vs[2][64][72];

    int lr = tid >> 1, lc = (tid & 1) * 32;

#define FA_ISSUE(BUF, K0)                                                          \
    do {                                                                           \
        const unsigned short* kp = g_kb + (size_t)(b * SEQ + (K0) + lr) * DM + h * HD + lc; \
        const unsigned short* vp = g_vb + (size_t)(b * SEQ + (K0) + lr) * DM + h * HD + lc; \
        uint32_t ka = smem_u32(&Ks[BUF][lr][lc]);                                  \
        uint32_t va = smem_u32(&Vs[BUF][lr][lc]);                                  \
        cp16(ka, kp); cp16(ka + 16, kp + 8); cp16(ka + 32, kp + 16); cp16(ka + 48, kp + 24); \
        cp16(va, vp); cp16(va + 16, vp + 8); cp16(va + 32, vp + 16); cp16(va + 48, vp + 24); \
    } while (0)

    FA_ISSUE(0, kt0 * 64);
    CP_COMMIT();

    {
        const unsigned short* qp = g_qb + (size_t)(b * SEQ + q0 + lr) * DM + h * HD + lc;
        *(uint4*)&Qs[lr][lc]      = *(const uint4*)(qp);
        *(uint4*)&Qs[lr][lc + 8]  = *(const uint4*)(qp + 8);
        *(uint4*)&Qs[lr][lc + 16] = *(const uint4*)(qp + 16);
        *(uint4*)&Qs[lr][lc + 24] = *(const uint4*)(qp + 24);
    }
    __syncthreads();

    uint32_t qa[4][4];
#pragma unroll
    for (int kc = 0; kc < 4; kc++) {
        uint32_t addr = smem_u32(&Qs[wq + (lane & 15)][kc * 16 + (lane >> 4) * 8]);
        ldsm_x4(qa[kc][0], qa[kc][1], qa[kc][2], qa[kc][3], addr);
    }

    float m_run[2] = {-1e30f, -1e30f};
    float l_run[2] = {0.f, 0.f};
    float oacc[8][4] = {};

    for (int kt = kt0; kt < kt1; kt++) {
        int k0 = kt * 64;
        int buf = (kt - kt0) & 1;
        CP_WAIT(0);
        __syncthreads();
        if (kt + 1 < kt1) { FA_ISSUE(buf ^ 1, k0 + 64); CP_COMMIT(); }

        float sacc[8][4] = {};
#pragma unroll
        for (int kc = 0; kc < 4; kc++) {
#pragma unroll
            for (int nb = 0; nb < 4; nb++) {
                uint32_t r0, r1, r2, r3;
                uint32_t addr = smem_u32(&Ks[buf][nb * 16 + (lane & 7) + ((lane >> 3) & 1) * 8]
                                            [kc * 16 + (lane >> 4) * 8]);
                ldsm_x4(r0, r1, r2, r3, addr);
                mma_bf16(sacc[nb * 2],     qa[kc][0], qa[kc][1], qa[kc][2], qa[kc][3], r0, r2);
                mma_bf16(sacc[nb * 2 + 1], qa[kc][0], qa[kc][1], qa[kc][2], qa[kc][3], r1, r3);
            }
        }

        bool diag = (kt == qt);
#pragma unroll
        for (int half = 0; half < 2; half++) {
            int qrow = q0 + wq + (lane >> 2) + half * 8;
            float vals[16];
#pragma unroll
            for (int nj = 0; nj < 8; nj++) {
                int colg = k0 + nj * 8 + 2 * (lane & 3);
                float v0 = sacc[nj][half * 2 + 0] * 0.125f;
                float v1 = sacc[nj][half * 2 + 1] * 0.125f;
                if (diag) {
                    if (colg > qrow) v0 = -1e30f;
                    if (colg + 1 > qrow) v1 = -1e30f;
                }
                vals[nj * 2] = v0;
                vals[nj * 2 + 1] = v1;
            }
            float tmx = vals[0];
#pragma unroll
            for (int i = 1; i < 16; i++) tmx = fmaxf(tmx, vals[i]);
            tmx = fmaxf(tmx, __shfl_xor_sync(0xffffffffu, tmx, 1));
            tmx = fmaxf(tmx, __shfl_xor_sync(0xffffffffu, tmx, 2));
            float mnew = fmaxf(m_run[half], tmx);
            float corr = __expf(m_run[half] - mnew);
            float rsum = 0.f;
#pragma unroll
            for (int i = 0; i < 8; i++) {
                float t0 = (vals[2 * i + 0] - mnew) * 1.44269504f;
                float t1 = (vals[2 * i + 1] - mnew) * 1.44269504f;
                __half2 ht = __floats2half2_rn(t0, t1);
                uint32_t pb = ex2_f16x2(*(uint32_t*)&ht);
                float2 p = __half22float2(*(__half2*)&pb);
                vals[2 * i + 0] = p.x;
                vals[2 * i + 1] = p.y;
                rsum += p.x + p.y;
            }
            rsum += __shfl_xor_sync(0xffffffffu, rsum, 1);
            rsum += __shfl_xor_sync(0xffffffffu, rsum, 2);
            l_run[half] = l_run[half] * corr + rsum;
            m_run[half] = mnew;
#pragma unroll
            for (int nj = 0; nj < 8; nj++) {
                oacc[nj][half * 2 + 0] *= corr;
                oacc[nj][half * 2 + 1] *= corr;
                sacc[nj][half * 2 + 0] = vals[nj * 2];
                sacc[nj][half * 2 + 1] = vals[nj * 2 + 1];
            }
        }

#pragma unroll
        for (int j = 0; j < 4; j++) {
            uint32_t pa0 = packbf(sacc[2 * j][0], sacc[2 * j][1]);
            uint32_t pa1 = packbf(sacc[2 * j][2], sacc[2 * j][3]);
            uint32_t pa2 = packbf(sacc[2 * j + 1][0], sacc[2 * j + 1][1]);
            uint32_t pa3 = packbf(sacc[2 * j + 1][2], sacc[2 * j + 1][3]);
#pragma unroll
            for (int nb = 0; nb < 2; nb++) {
                uint32_t b0, b1, b2, b3;
                uint32_t addr = smem_u32(&Vs[buf][j * 16 + (lane & 15)][nb * 32 + (lane >> 4) * 8]);
                ldsm_x4_t(b0, b1, b2, b3, addr);
                mma_bf16(oacc[nb * 4 + 0], pa0, pa1, pa2, pa3, b0, b1);
                mma_bf16(oacc[nb * 4 + 1], pa0, pa1, pa2, pa3, b2, b3);
                addr = smem_u32(&Vs[buf][j * 16 + (lane & 15)][nb * 32 + 16 + (lane >> 4) * 8]);
                ldsm_x4_t(b0, b1, b2, b3, addr);
                mma_bf16(oacc[nb * 4 + 2], pa0, pa1, pa2, pa3, b0, b1);
                mma_bf16(oacc[nb * 4 + 3], pa0, pa1, pa2, pa3, b2, b3);
            }
        }
    }
#undef FA_ISSUE

    float* po = g_po + (((size_t)chunk * BH + bh) * 16 + (size_t)qt) * 4096;
#pragma unroll
    for (int half = 0; half < 2; half++) {
        int rloc = wq + (lane >> 2) + half * 8;
        if ((lane & 3) == 0) pml[rloc] = make_float2(m_run[half], l_run[half]);
#pragma unroll
        for (int nj = 0; nj < 8; nj++) {
            int col = nj * 8 + 2 * (lane & 3);
            *(float2*)&po[rloc * 64 + col] =
                make_float2(oacc[nj][half * 2 + 0], oacc[nj][half * 2 + 1]);
        }
    }
}

// ---------------- flash combine ----------------
__global__ __launch_bounds__(256)
void flash_combine_kernel() {
    int qt = blockIdx.x, bh = blockIdx.y;
    int b = bh / NH, h = bh % NH;
    int q0 = qt * 64;
    int tid = threadIdx.x;
    int r = tid >> 2, cseg = (tid & 3) * 16;

    float2 ml0 = g_pml[((size_t)0 * BH + bh) * SEQ + q0 + r];
    float2 ml1 = g_pml[((size_t)1 * BH + bh) * SEQ + q0 + r];
    bool v1 = ml1.y > 0.f;
    float mstar = fmaxf(ml0.x, v1 ? ml1.x : -1e30f);
    float e0 = __expf(ml0.x - mstar);
    float e1 = v1 ? __expf(ml1.x - mstar) : 0.f;
    float inv = 1.0f / (ml0.y * e0 + (v1 ? ml1.y * e1 : 0.f));

    const float* po0 = g_po + (((size_t)0 * BH + bh) * 16 + (size_t)qt) * 4096 + r * 64;
    const float* po1 = g_po + (((size_t)1 * BH + bh) * 16 + (size_t)qt) * 4096 + r * 64;
    unsigned short* dst = g_attnb + (size_t)(b * SEQ + q0 + r) * DM + h * HD;
#pragma unroll
    for (int i = 0; i < 4; i++) {
        int col = cseg + i * 4;
        float4 o0 = *(const float4*)(po0 + col);
        float4 o1 = v1 ? *(const float4*)(po1 + col) : make_float4(0.f, 0.f, 0.f, 0.f);
        float vx = (o0.x * e0 + o1.x * e1) * inv;
        float vy = (o0.y * e0 + o1.y * e1) * inv;
        float vz = (o0.z * e0 + o1.z * e1) * inv;
        float vw = (o0.w * e0 + o1.w * e1) * inv;
        *(uint2*)&dst[col] = make_uint2(packbf(vx, vy), packbf(vz, vw));
    }
}

// ---------------- layernorm: 192 threads, float4, single-pass sum/sumsq ---------
__global__ __launch_bounds__(192)
void ln_kernel(const float* __restrict__ x, const float* __restrict__ gam,
               const float* __restrict__ bet, float* __restrict__ yf,
               unsigned short* __restrict__ yb) {
    int row = blockIdx.x;
    int tid = threadIdx.x;  // 192 = DM/4
    __shared__ float rs[6], rs2[6];
    float4 v = ((const float4*)(x + (size_t)row * DM))[tid];
    float s  = v.x + v.y + v.z + v.w;
    float s2 = v.x * v.x + v.y * v.y + v.z * v.z + v.w * v.w;
#pragma unroll
    for (int o = 16; o > 0; o >>= 1) {
        s  += __shfl_xor_sync(0xffffffffu, s,  o);
        s2 += __shfl_xor_sync(0xffffffffu, s2, o);
    }
    if ((tid & 31) == 0) { rs[tid >> 5] = s; rs2[tid >> 5] = s2; }
    __syncthreads();
    float ts = 0.f, ts2 = 0.f;
#pragma unroll
    for (int i = 0; i < 6; i++) { ts += rs[i]; ts2 += rs2[i]; }
    float m = ts * (1.0f / DM);
    float var = ts2 * (1.0f / DM) - m * m;
    float r = rsqrtf(var + 1e-5f);
    float4 g4 = ((const float4*)gam)[tid];
    float4 b4 = ((const float4*)bet)[tid];
    float4 o4;
    o4.x = (v.x - m) * r * g4.x + b4.x;
    o4.y = (v.y - m) * r * g4.y + b4.y;
    o4.z = (v.z - m) * r * g4.z + b4.z;
    o4.w = (v.w - m) * r * g4.w + b4.w;
    if (yf) ((float4*)(yf + (size_t)row * DM))[tid] = o4;
    *(uint2*)(yb + (size_t)row * DM + tid * 4) =
        make_uint2(packbf(o4.x, o4.y), packbf(o4.z, o4.w));
}

// ---------------- router ----------------
__global__ void router_kernel(const float* __restrict__ Wr, const float* __restrict__ br) {
    int t = blockIdx.x, tid = threadIdx.x;  // 64 threads
    float acc[NEXP] = {};
    const float* xr = g_xn2 + (size_t)t * DM;
    for (int d = tid; d < DM; d += 64) {
        float xv = xr[d];
        const float* w = Wr + (size_t)d * NEXP;
#pragma unroll
        for (int e = 0; e < NEXP; e++) acc[e] += xv * w[e];
    }
    __shared__ float sh[64][NEXP + 1];
#pragma unroll
    for (int e = 0; e < NEXP; e++) sh[tid][e] = acc[e];
    __syncthreads();
    if (tid < NEXP) {
        float s = br[tid];
        for (int i = 0; i < 64; i++) s += sh[i][tid];
        sh[0][tid] = s;
    }
    __syncthreads();
    if (tid == 0) {
        float l[NEXP];
#pragma unroll
        for (int e = 0; e < NEXP; e++) l[e] = sh[0][e];
        int i1 = 0;
        for (int e = 1; e < NEXP; e++) if (l[e] > l[i1]) i1 = e;
        int i2 = (i1 == 0) ? 1 : 0;
        for (int e = 0; e < NEXP; e++) if (e != i1 && l[e] > l[i2]) i2 = e;
        float g1 = 1.0f / (1.0f + expf(l[i2] - l[i1]));
        float g2 = 1.0f - g1;
        g_top_e[2 * t] = i1; g_top_g[2 * t] = g1;
        g_top_e[2 * t + 1] = i2; g_top_g[2 * t + 1] = g2;
        atomicAdd(&g_cnt[i1], 1);
        atomicAdd(&g_cnt[i2], 1);
    }
}

__global__ void offsets_kernel() {
    if (threadIdx.x == 0) {
        int acc = 0;
#pragma unroll
        for (int e = 0; e < NEXP; e++) { g_off[e] = acc; acc += g_cnt[e]; }
    }
}

__global__ void scatter_kernel() {
    int i = blockIdx.x * 256 + threadIdx.x;
    if (i >= NSLOTS) return;
    int e = g_top_e[i];
    int p = atomicAdd(&g_fill[e], 1);
    int slot = g_off[e] + p;
    g_slot_tok[slot] = i >> 1;
    g_slot_gate[slot] = g_top_g[i];
}

// ---------------- launch ----------------
extern "C" void kernel_launch(void* const* d_in, const int* in_sizes, int n_in,
                              void* d_out, int out_size) {
    const float* x     = (const float*)d_in[0];
    const float* ln1_g = (const float*)d_in[1];
    const float* ln1_b = (const float*)d_in[2];
    const float* Wq    = (const float*)d_in[3];
    const float* Wk    = (const float*)d_in[4];
    const float* Wv    = (const float*)d_in[5];
    const float* Wo    = (const float*)d_in[6];
    const float* bo    = (const float*)d_in[7];
    const float* ln2_g = (const float*)d_in[8];
    const float* ln2_b = (const float*)d_in[9];
    const float* Wr    = (const float*)d_in[10];
    const float* br    = (const float*)d_in[11];
    const float* W1    = (const float*)d_in[12];
    const float* b1    = (const float*)d_in[13];
    const float* W2    = (const float*)d_in[14];
    const float* b2    = (const float*)d_in[15];
    float* out = (float*)d_out;

    float* xn2_p;
    unsigned short *xn1b_p, *xn2b_p, *w1b_p, *w2b_p;
    cudaGetSymbolAddress((void**)&xn2_p, g_xn2);
    cudaGetSymbolAddress((void**)&xn1b_p, g_xn1b);
    cudaGetSymbolAddress((void**)&xn2b_p, g_xn2b);
    cudaGetSymbolAddress((void**)&w1b_p, g_w1b);
    cudaGetSymbolAddress((void**)&w2b_p, g_w2b);

    const int SM128 = (4 * 128 * 40 + 4 * 4352) * 2;  // 75776 B
    const int SM64  = (4 * 64 * 40 + 4 * 4352) * 2;   // 55296 B
    cudaFuncSetAttribute((const void*)bgemm<1, 64>,  cudaFuncAttributeMaxDynamicSharedMemorySize, SM64);
    cudaFuncSetAttribute((const void*)bgemm<2, 128>, cudaFuncAttributeMaxDynamicSharedMemorySize, SM128);
    cudaFuncSetAttribute((const void*)bgemm<3, 128>, cudaFuncAttributeMaxDynamicSharedMemorySize, SM128);
    cudaFuncSetAttribute((const void*)bgemm<4, 64>,  cudaFuncAttributeMaxDynamicSharedMemorySize, SM64);

    zero_cnt_kernel<<<1, 32>>>();
    {
        const size_t total = 4 * ((size_t)DM * DM / 8) + 2 * ((size_t)NEXP * DM * DFF / 8);
        cvt_all_kernel<<<(unsigned)((total + 255) / 256), 256>>>(Wq, Wk, Wv, Wo, W1, W2, w1b_p, w2b_p);
    }

    ln_kernel<<<TOKENS, 192>>>(x, ln1_g, ln1_b, nullptr, xn1b_p);

    // fused QKV (bf16 out), TM=64 -> 576 CTAs
    bgemm<4, 64><<<dim3(18, TOKENS / 64), 256, SM64>>>(nullptr, nullptr, nullptr, DM, DM);

    // split-KV flash + combine
    flash_attn_kernel<<<dim3(16, BH, 2), 128>>>();
    flash_combine_kernel<<<dim3(16, BH), 256>>>();

    // h = x + attn @ Wo + bo -> d_out, TM=64 -> 192 CTAs
    bgemm<1, 64><<<dim3(DM / 128, TOKENS / 64), 256, SM64>>>(bo, x, out, DM, DM);

    ln_kernel<<<TOKENS, 192>>>(out, ln2_g, ln2_b, xn2_p, xn2b_p);

    router_kernel<<<TOKENS, 64>>>(Wr, br);
    offsets_kernel<<<1, 32>>>();
    scatter_kernel<<<(NSLOTS + 255) / 256, 256>>>();

    bgemm<2, 128><<<dim3(DFF / 128, TOKENS / 128, NEXP), 256, SM128>>>(b1, nullptr, nullptr, DFF, DM);
    bgemm<3, 128><<<dim3(DM / 128, TOKENS / 128, NEXP * 2), 256, SM128>>>(b2, nullptr, out, DM, DFF);
}